// round 1
// baseline (speedup 1.0000x reference)
#include <cuda_runtime.h>
#include <math.h>

#define Bb 8
#define Tt 2048
#define Cc 1024
#define NFr 64
#define MM (Bb*Tt)          /* 16384 rows */
#define EPSV 1e-6f

// Scratch (allocation-free rule: __device__ globals)
__device__ float g_q [MM * Cc];       // 64 MB
__device__ float g_q2[MM * Cc];       // 64 MB
__device__ float g_v [MM * Cc];       // 64 MB
__device__ float g_sc[MM * 2 * NFr];  //  8 MB

// ---------------------------------------------------------------------------
// Generic 64x64 tiled fp32 GEMM. MODE 0: attn (split cols -> q, v).
//                                MODE 1: proj (A element = q*v), single out.
// ---------------------------------------------------------------------------
template<int MODE>
__global__ __launch_bounds__(256)
void gemm64(const float* __restrict__ A, const float* __restrict__ A2,
            const float* __restrict__ W, const float* __restrict__ bias,
            float* __restrict__ O0, float* __restrict__ O1,
            int Ndim, int Kdim)
{
    __shared__ float As[16][64];   // transposed: As[k][m]
    __shared__ float Bs[16][64];
    const int tid = threadIdx.x;
    const int tx = tid & 15, ty = tid >> 4;
    const int row0 = blockIdx.y * 64;
    const int n0   = blockIdx.x * 64;

    float acc[4][4] = {};

    for (int k0 = 0; k0 < Kdim; k0 += 16) {
        #pragma unroll
        for (int i = 0; i < 4; i++) {
            int e = tid + 256 * i;            // 1024 elems: 64 m x 16 k
            int m = e >> 4, k = e & 15;
            size_t gi = (size_t)(row0 + m) * Kdim + k0 + k;
            float av = A[gi];
            if (MODE == 1) av *= A2[gi];
            As[k][m] = av;
        }
        #pragma unroll
        for (int i = 0; i < 4; i++) {
            int e = tid + 256 * i;            // 16 k x 64 n
            int k = e >> 6, n = e & 63;
            Bs[k][n] = W[(size_t)(k0 + k) * Ndim + n0 + n];
        }
        __syncthreads();
        #pragma unroll
        for (int kk = 0; kk < 16; kk++) {
            float4 a4 = *(const float4*)&As[kk][ty * 4];
            float4 b4 = *(const float4*)&Bs[kk][tx * 4];
            float a[4] = {a4.x, a4.y, a4.z, a4.w};
            float b[4] = {b4.x, b4.y, b4.z, b4.w};
            #pragma unroll
            for (int i = 0; i < 4; i++)
                #pragma unroll
                for (int j = 0; j < 4; j++)
                    acc[i][j] = fmaf(a[i], b[j], acc[i][j]);
        }
        __syncthreads();
    }

    const int nb = n0 + tx * 4;
    float4 bia = *(const float4*)&bias[nb];
    float bb[4] = {bia.x, bia.y, bia.z, bia.w};
    #pragma unroll
    for (int i = 0; i < 4; i++) {
        int r = row0 + ty * 4 + i;
        float4 o = make_float4(acc[i][0] + bb[0], acc[i][1] + bb[1],
                               acc[i][2] + bb[2], acc[i][3] + bb[3]);
        if (MODE == 0) {
            if (n0 < Cc) *(float4*)&O0[(size_t)r * Cc + nb]       = o;
            else         *(float4*)&O1[(size_t)r * Cc + nb - Cc]  = o;
        } else {
            *(float4*)&O0[(size_t)r * Ndim + nb] = o;
        }
    }
}

// ---------------------------------------------------------------------------
// Scan step, stage 1: f = [shift(q), q] @ freq_W + freq_b ; sc = [sin f, cos f]
// Shift is folded into the A-tile load (no materialized concat).
// ---------------------------------------------------------------------------
__global__ __launch_bounds__(256)
void freq_kernel(const float* __restrict__ qin,
                 const float* __restrict__ freq_W,
                 const float* __restrict__ freq_b,
                 const float* __restrict__ identity,
                 float* __restrict__ sc, int nShift)
{
    __shared__ float As[32][64];   // As[k][m]
    __shared__ float Bs[32][64];
    const int tid = threadIdx.x;
    const int tx = tid & 15, ty = tid >> 4;
    const int row0 = blockIdx.x * 64;

    float acc[4][4] = {};

    for (int k0 = 0; k0 < 2 * Cc; k0 += 32) {
        #pragma unroll
        for (int i = 0; i < 8; i++) {
            int e = tid + 256 * i;            // 2048 elems: 64 m x 32 k
            int m = e >> 5, k = e & 31;
            int r = row0 + m;
            int kg = k0 + k;
            float v;
            if (kg < Cc) {
                int t = r & (Tt - 1);
                v = (t >= nShift) ? qin[(size_t)(r - nShift) * Cc + kg]
                                  : identity[kg];
            } else {
                v = qin[(size_t)r * Cc + (kg - Cc)];
            }
            As[k][m] = v;
        }
        #pragma unroll
        for (int i = 0; i < 8; i++) {
            int e = tid + 256 * i;            // 32 k x 64 n
            int k = e >> 6, n = e & 63;
            Bs[k][n] = freq_W[(size_t)(k0 + k) * NFr + n];
        }
        __syncthreads();
        #pragma unroll
        for (int kk = 0; kk < 32; kk++) {
            float4 a4 = *(const float4*)&As[kk][ty * 4];
            float4 b4 = *(const float4*)&Bs[kk][tx * 4];
            float a[4] = {a4.x, a4.y, a4.z, a4.w};
            float b[4] = {b4.x, b4.y, b4.z, b4.w};
            #pragma unroll
            for (int i = 0; i < 4; i++)
                #pragma unroll
                for (int j = 0; j < 4; j++)
                    acc[i][j] = fmaf(a[i], b[j], acc[i][j]);
        }
        __syncthreads();
    }

    #pragma unroll
    for (int i = 0; i < 4; i++) {
        int r = row0 + ty * 4 + i;
        #pragma unroll
        for (int j = 0; j < 4; j++) {
            int n = tx * 4 + j;
            float f = acc[i][j] + freq_b[n];
            float s, c;
            sincosf(f, &s, &c);
            sc[(size_t)r * 128 + n]      = s;
            sc[(size_t)r * 128 + 64 + n] = c;
        }
    }
}

// ---------------------------------------------------------------------------
// Scan step, stage 2: q' = mmnorm(sc @ out_W + out_b).  16 rows/block,
// each thread owns 4 cols across all 16 rows; K=128 fully resident in smem.
// mmnorm fused via smem + shuffle max-abs reduction.
// ---------------------------------------------------------------------------
__global__ __launch_bounds__(256, 2)
void out_kernel(const float* __restrict__ sc,
                const float* __restrict__ out_W,
                const float* __restrict__ out_b,
                float* __restrict__ qout)
{
    __shared__ float scs[16][128];
    __shared__ float pm[16][264];      // padded partial-max matrix
    __shared__ float rinv[16];
    const int tid = threadIdx.x;
    const int row0 = blockIdx.x * 16;

    #pragma unroll
    for (int i = 0; i < 8; i++) {
        int e = tid + 256 * i;
        scs[e >> 7][e & 127] = sc[(size_t)row0 * 128 + e];
    }
    __syncthreads();

    float acc[16][4] = {};
    const float4* W4 = (const float4*)out_W;
    for (int k = 0; k < 128; k += 4) {
        float4 w0 = W4[(size_t)(k + 0) * 256 + tid];
        float4 w1 = W4[(size_t)(k + 1) * 256 + tid];
        float4 w2 = W4[(size_t)(k + 2) * 256 + tid];
        float4 w3 = W4[(size_t)(k + 3) * 256 + tid];
        #pragma unroll
        for (int r = 0; r < 16; r++) {
            float4 s = *(const float4*)&scs[r][k];
            acc[r][0] = fmaf(s.x, w0.x, acc[r][0]);
            acc[r][1] = fmaf(s.x, w0.y, acc[r][1]);
            acc[r][2] = fmaf(s.x, w0.z, acc[r][2]);
            acc[r][3] = fmaf(s.x, w0.w, acc[r][3]);
            acc[r][0] = fmaf(s.y, w1.x, acc[r][0]);
            acc[r][1] = fmaf(s.y, w1.y, acc[r][1]);
            acc[r][2] = fmaf(s.y, w1.z, acc[r][2]);
            acc[r][3] = fmaf(s.y, w1.w, acc[r][3]);
            acc[r][0] = fmaf(s.z, w2.x, acc[r][0]);
            acc[r][1] = fmaf(s.z, w2.y, acc[r][1]);
            acc[r][2] = fmaf(s.z, w2.z, acc[r][2]);
            acc[r][3] = fmaf(s.z, w2.w, acc[r][3]);
            acc[r][0] = fmaf(s.w, w3.x, acc[r][0]);
            acc[r][1] = fmaf(s.w, w3.y, acc[r][1]);
            acc[r][2] = fmaf(s.w, w3.z, acc[r][2]);
            acc[r][3] = fmaf(s.w, w3.w, acc[r][3]);
        }
    }

    float4 b4 = ((const float4*)out_b)[tid];
    float bb[4] = {b4.x, b4.y, b4.z, b4.w};
    #pragma unroll
    for (int r = 0; r < 16; r++) {
        float m = 0.0f;
        #pragma unroll
        for (int j = 0; j < 4; j++) {
            acc[r][j] += bb[j];
            m = fmaxf(m, fabsf(acc[r][j]));
        }
        pm[r][tid] = m;
    }
    __syncthreads();

    const int wid = tid >> 5, lane = tid & 31;
    {
        #pragma unroll
        for (int rr = 0; rr < 2; rr++) {
            int r = wid * 2 + rr;
            float m = pm[r][lane];
            #pragma unroll
            for (int s = 1; s < 8; s++) m = fmaxf(m, pm[r][lane + 32 * s]);
            #pragma unroll
            for (int o = 16; o > 0; o >>= 1)
                m = fmaxf(m, __shfl_xor_sync(0xffffffff, m, o));
            if (lane == 0) rinv[r] = 1.0f / (m + EPSV);
        }
    }
    __syncthreads();

    #pragma unroll
    for (int r = 0; r < 16; r++) {
        float sc_ = rinv[r];
        float4 o = make_float4(acc[r][0] * sc_, acc[r][1] * sc_,
                               acc[r][2] * sc_, acc[r][3] * sc_);
        ((float4*)qout)[(size_t)(row0 + r) * 256 + tid] = o;
    }
}

// ---------------------------------------------------------------------------
extern "C" void kernel_launch(void* const* d_in, const int* in_sizes, int n_in,
                              void* d_out, int out_size)
{
    (void)in_sizes; (void)n_in; (void)out_size;
    const float* x        = (const float*)d_in[0];
    const float* attn_W   = (const float*)d_in[1];
    const float* attn_b   = (const float*)d_in[2];
    const float* freq_W   = (const float*)d_in[3];
    const float* freq_b   = (const float*)d_in[4];
    const float* out_W    = (const float*)d_in[5];
    const float* out_b    = (const float*)d_in[6];
    const float* proj_W   = (const float*)d_in[7];
    const float* proj_b   = (const float*)d_in[8];
    const float* identity = (const float*)d_in[9];

    float *q, *q2, *v, *sc;
    cudaGetSymbolAddress((void**)&q,  g_q);
    cudaGetSymbolAddress((void**)&q2, g_q2);
    cudaGetSymbolAddress((void**)&v,  g_v);
    cudaGetSymbolAddress((void**)&sc, g_sc);

    // qv = x @ attn_W + attn_b, split into q | v
    {
        dim3 grid(2 * Cc / 64, MM / 64);
        gemm64<0><<<grid, 256>>>(x, nullptr, attn_W, attn_b, q, v, 2 * Cc, Cc);
    }

    // log-scan: 11 sequential steps
    float* cur = q;
    float* nxt = q2;
    for (int n = 1; n < Tt; n <<= 1) {
        freq_kernel<<<MM / 64, 256>>>(cur, freq_W, freq_b, identity, sc, n);
        out_kernel<<<MM / 16, 256>>>(sc, out_W, out_b, nxt);
        float* t = cur; cur = nxt; nxt = t;
    }

    // out = (q * v) @ proj_W + proj_b
    {
        dim3 grid(Cc / 64, MM / 64);
        gemm64<1><<<grid, 256>>>(cur, v, proj_W, proj_b, (float*)d_out, nullptr,
                                 Cc, Cc);
    }
}

// round 5
// speedup vs baseline: 3.8587x; 3.8587x over previous
#include <cuda_runtime.h>
#include <cuda_bf16.h>
#include <math.h>
#include <stdint.h>

#define MM   16384
#define Cc   1024
#define Tt   2048
#define EPSV 1e-6f

// ---------------------------------------------------------------------------
// Scratch (__device__ globals; no allocation allowed)
// ---------------------------------------------------------------------------
__device__ __nv_bfloat16 g_xh[MM * Cc], g_xl[MM * Cc];
__device__ __nv_bfloat16 g_qh[MM * Cc], g_ql[MM * Cc];
__device__ float         g_v [MM * Cc];
__device__ float         g_z [MM * Cc];
__device__ __nv_bfloat16 g_sch[MM * 128], g_scl[MM * 128];
__device__ float         g_pmax[8 * MM];
__device__ __nv_bfloat16 g_aWh[2048 * 1024], g_aWl[2048 * 1024];
__device__ __nv_bfloat16 g_fWh[64 * 2048],   g_fWl[64 * 2048];
__device__ __nv_bfloat16 g_oWh[1024 * 128],  g_oWl[1024 * 128];
__device__ __nv_bfloat16 g_pWh[1024 * 1024], g_pWl[1024 * 1024];
__device__ __nv_bfloat16 g_idh[Cc], g_idl[Cc];

// ---------------------------------------------------------------------------
__device__ __forceinline__ uint32_t smem_u32(const void* p) {
    uint32_t a;
    asm("{ .reg .u64 t; cvta.to.shared.u64 t, %1; cvt.u32.u64 %0, t; }"
        : "=r"(a) : "l"(p));
    return a;
}
__device__ __forceinline__ void cp16(uint32_t dst, const void* src) {
    asm volatile("cp.async.cg.shared.global [%0], [%1], 16;"
                 :: "r"(dst), "l"(src));
}
#define CP_COMMIT() asm volatile("cp.async.commit_group;")
#define CP_WAIT1()  asm volatile("cp.async.wait_group 1;")
#define CP_WAIT0()  asm volatile("cp.async.wait_group 0;")

__device__ __forceinline__ void ldmA(uint32_t* a, uint32_t addr) {
    asm volatile("ldmatrix.sync.aligned.m8n8.x4.shared.b16 {%0,%1,%2,%3}, [%4];"
                 : "=r"(a[0]), "=r"(a[1]), "=r"(a[2]), "=r"(a[3]) : "r"(addr));
}
__device__ __forceinline__ void ldmB(uint32_t* b, uint32_t addr) {
    asm volatile("ldmatrix.sync.aligned.m8n8.x2.shared.b16 {%0,%1}, [%2];"
                 : "=r"(b[0]), "=r"(b[1]) : "r"(addr));
}
__device__ __forceinline__ void mma16816(float* c, const uint32_t* a,
                                         const uint32_t* b) {
    asm volatile("mma.sync.aligned.m16n8k16.row.col.f32.bf16.bf16.f32 "
                 "{%0,%1,%2,%3}, {%4,%5,%6,%7}, {%8,%9}, {%0,%1,%2,%3};"
                 : "+f"(c[0]), "+f"(c[1]), "+f"(c[2]), "+f"(c[3])
                 : "r"(a[0]), "r"(a[1]), "r"(a[2]), "r"(a[3]),
                   "r"(b[0]), "r"(b[1]));
}
__device__ __forceinline__ void split2(float a, float b, uint32_t& hi, uint32_t& lo) {
    __nv_bfloat16 ha = __float2bfloat16(a), hb = __float2bfloat16(b);
    __nv_bfloat162 hp = __halves2bfloat162(ha, hb);
    __nv_bfloat162 lp = __halves2bfloat162(
        __float2bfloat16(a - __bfloat162float(ha)),
        __float2bfloat16(b - __bfloat162float(hb)));
    hi = *(uint32_t*)&hp;
    lo = *(uint32_t*)&lp;
}

// ---------------------------------------------------------------------------
// Split-precision bf16 mma.sync GEMM.  D[128, BN] per CTA.
// K runs 3 segments: (Ah,Bh), (Ah,Bl), (Al,Bh).  B is pre-transposed [N][K].
// MODE 0: attn  (cols<1024 -> qh/ql bf16 split, else v fp32)
// MODE 1: freq  (A = [shift(q), q] folded into load; sincos -> sch/scl)
// MODE 2: out   (fp32 z + per-block row-max partials)
// MODE 3: proj  (plain fp32 out + bias)
// ---------------------------------------------------------------------------
template<int MODE, int BN, int KB>
__global__ __launch_bounds__(256)
void mma_gemm(const __nv_bfloat16* __restrict__ Ah, const __nv_bfloat16* __restrict__ Al,
              const __nv_bfloat16* __restrict__ idh, const __nv_bfloat16* __restrict__ idl,
              const __nv_bfloat16* __restrict__ Bh, const __nv_bfloat16* __restrict__ Bl,
              const float* __restrict__ bias,
              float* __restrict__ outf,
              __nv_bfloat16* __restrict__ outh, __nv_bfloat16* __restrict__ outl,
              float* __restrict__ pmax, int nShift)
{
    constexpr int BK     = 32;
    constexpr int STAGES = 3;
    constexpr int SEG_KT = KB / BK;
    constexpr int KT     = 3 * SEG_KT;
    constexpr int LDS    = BK + 8;                 // halves, +16B pad
    constexpr int ASTG   = 128 * LDS * 2;          // bytes
    constexpr int BSTG   = BN * LDS * 2;
    constexpr int WN     = BN / 4;                 // warp N extent
    constexpr int NI     = WN / 8;                 // n-tiles per warp

    extern __shared__ __align__(128) char smem[];
    const uint32_t sA = smem_u32(smem);
    const uint32_t sB = sA + STAGES * ASTG;

    const int tid  = threadIdx.x;
    const int wid  = tid >> 5, lane = tid & 31;
    const int wm   = wid >> 2, wn = wid & 3;       // 2 x 4 warp grid
    const int row0 = blockIdx.y * 128;
    const int n0   = blockIdx.x * BN;
    const int ALD  = (MODE == 2) ? 128 : Cc;       // A leading dim (elements)

    float acc[4][NI][4];
    #pragma unroll
    for (int mi = 0; mi < 4; mi++)
        #pragma unroll
        for (int ni = 0; ni < NI; ni++)
            #pragma unroll
            for (int r = 0; r < 4; r++) acc[mi][ni][r] = 0.0f;

    auto load_tiles = [&](int kt, int stage) {
        if (kt >= KT) return;
        const int seg = kt / SEG_KT;
        const int kb  = (kt - seg * SEG_KT) * BK;
        const __nv_bfloat16* Asrc = (seg < 2) ? Ah : Al;
        const int chunk = tid & 3;                 // 4 x 16B per 32-half row
        const int kg    = kb + chunk * 8;
        #pragma unroll
        for (int p = 0; p < 2; p++) {
            const int row = (tid >> 2) + p * 64;
            const int rg  = row0 + row;
            const __nv_bfloat16* src;
            if (MODE == 1) {
                if (kg < Cc) {
                    int t = rg & (Tt - 1);
                    src = (t >= nShift) ? Asrc + (size_t)(rg - nShift) * Cc + kg
                                        : ((seg < 2) ? idh : idl) + kg;
                } else {
                    src = Asrc + (size_t)rg * Cc + (kg - Cc);
                }
            } else {
                src = Asrc + (size_t)rg * ALD + kg;
            }
            cp16(sA + stage * ASTG + (row * LDS + chunk * 8) * 2, src);
        }
        const __nv_bfloat16* Bsrc = (seg == 1) ? Bl : Bh;
        #pragma unroll
        for (int p = 0; p < BN / 64; p++) {
            const int row = (tid >> 2) + p * 64;   // n index
            cp16(sB + stage * BSTG + (row * LDS + chunk * 8) * 2,
                 Bsrc + (size_t)(n0 + row) * KB + kg);
        }
    };

    // prologue
    #pragma unroll
    for (int s = 0; s < STAGES - 1; s++) { load_tiles(s, s); CP_COMMIT(); }

    for (int kt = 0; kt < KT; kt++) {
        CP_WAIT1();
        __syncthreads();
        load_tiles(kt + STAGES - 1, (kt + STAGES - 1) % STAGES);
        CP_COMMIT();

        const int stage = kt % STAGES;
        const uint32_t aBase = sA + stage * ASTG;
        const uint32_t bBase = sB + stage * BSTG;
        #pragma unroll
        for (int ks = 0; ks < 2; ks++) {
            uint32_t af[4][4];
            #pragma unroll
            for (int mi = 0; mi < 4; mi++)
                ldmA(af[mi], aBase +
                     ((wm * 64 + mi * 16 + (lane & 15)) * LDS +
                      ks * 16 + (lane >> 4) * 8) * 2);
            uint32_t bf[NI][2];
            #pragma unroll
            for (int ni = 0; ni < NI; ni++)
                ldmB(bf[ni], bBase +
                     ((wn * WN + ni * 8 + (lane & 7)) * LDS +
                      ks * 16 + ((lane >> 3) & 1) * 8) * 2);
            #pragma unroll
            for (int mi = 0; mi < 4; mi++)
                #pragma unroll
                for (int ni = 0; ni < NI; ni++)
                    mma16816(acc[mi][ni], af[mi], bf[ni]);
        }
    }
    CP_WAIT0();
    __syncthreads();

    // ---- epilogue ----
    float* pm = (float*)smem;                      // [128][4] row-max partials
    float rmax[4][2];
    #pragma unroll
    for (int mi = 0; mi < 4; mi++) { rmax[mi][0] = 0.0f; rmax[mi][1] = 0.0f; }

    #pragma unroll
    for (int mi = 0; mi < 4; mi++) {
        const int R0 = row0 + wm * 64 + mi * 16 + (lane >> 2);
        const int R1 = R0 + 8;
        #pragma unroll
        for (int ni = 0; ni < NI; ni++) {
            const int c  = wn * WN + ni * 8 + 2 * (lane & 3);
            const int gc = n0 + c;
            const float b0 = bias[gc], b1 = bias[gc + 1];
            float v0 = acc[mi][ni][0] + b0, v1 = acc[mi][ni][1] + b1;
            float v2 = acc[mi][ni][2] + b0, v3 = acc[mi][ni][3] + b1;
            if (MODE == 0) {
                if (gc < Cc) {
                    uint32_t hi, lo;
                    split2(v0, v1, hi, lo);
                    *(uint32_t*)&outh[(size_t)R0 * Cc + gc] = hi;
                    *(uint32_t*)&outl[(size_t)R0 * Cc + gc] = lo;
                    split2(v2, v3, hi, lo);
                    *(uint32_t*)&outh[(size_t)R1 * Cc + gc] = hi;
                    *(uint32_t*)&outl[(size_t)R1 * Cc + gc] = lo;
                } else {
                    *(float2*)&outf[(size_t)R0 * Cc + gc - Cc] = make_float2(v0, v1);
                    *(float2*)&outf[(size_t)R1 * Cc + gc - Cc] = make_float2(v2, v3);
                }
            } else if (MODE == 1) {
                float s0, c0, s1, c1, s2, c2, s3, c3;
                sincosf(v0, &s0, &c0); sincosf(v1, &s1, &c1);
                sincosf(v2, &s2, &c2); sincosf(v3, &s3, &c3);
                uint32_t hi, lo;
                split2(s0, s1, hi, lo);
                *(uint32_t*)&outh[(size_t)R0 * 128 + gc] = hi;
                *(uint32_t*)&outl[(size_t)R0 * 128 + gc] = lo;
                split2(c0, c1, hi, lo);
                *(uint32_t*)&outh[(size_t)R0 * 128 + 64 + gc] = hi;
                *(uint32_t*)&outl[(size_t)R0 * 128 + 64 + gc] = lo;
                split2(s2, s3, hi, lo);
                *(uint32_t*)&outh[(size_t)R1 * 128 + gc] = hi;
                *(uint32_t*)&outl[(size_t)R1 * 128 + gc] = lo;
                split2(c2, c3, hi, lo);
                *(uint32_t*)&outh[(size_t)R1 * 128 + 64 + gc] = hi;
                *(uint32_t*)&outl[(size_t)R1 * 128 + 64 + gc] = lo;
            } else {
                *(float2*)&outf[(size_t)R0 * Cc + gc] = make_float2(v0, v1);
                *(float2*)&outf[(size_t)R1 * Cc + gc] = make_float2(v2, v3);
                if (MODE == 2) {
                    rmax[mi][0] = fmaxf(rmax[mi][0], fmaxf(fabsf(v0), fabsf(v1)));
                    rmax[mi][1] = fmaxf(rmax[mi][1], fmaxf(fabsf(v2), fabsf(v3)));
                }
            }
        }
    }

    if (MODE == 2) {
        #pragma unroll
        for (int mi = 0; mi < 4; mi++) {
            float m0 = rmax[mi][0], m1 = rmax[mi][1];
            #pragma unroll
            for (int off = 1; off < 4; off <<= 1) {
                m0 = fmaxf(m0, __shfl_xor_sync(0xffffffff, m0, off));
                m1 = fmaxf(m1, __shfl_xor_sync(0xffffffff, m1, off));
            }
            if ((lane & 3) == 0) {
                int lr = wm * 64 + mi * 16 + (lane >> 2);
                pm[lr * 4 + wn]       = m0;
                pm[(lr + 8) * 4 + wn] = m1;
            }
        }
        __syncthreads();
        if (tid < 128) {
            float m = fmaxf(fmaxf(pm[tid * 4], pm[tid * 4 + 1]),
                            fmaxf(pm[tid * 4 + 2], pm[tid * 4 + 3]));
            pmax[(size_t)blockIdx.x * MM + row0 + tid] = m;
        }
    }
}

// ---------------------------------------------------------------------------
// mmnorm finalize: q = z / (rowmax + eps), re-split into bf16 hi/lo.
// ---------------------------------------------------------------------------
__global__ __launch_bounds__(256)
void normalize_kernel(const float* __restrict__ z, const float* __restrict__ pmax,
                      __nv_bfloat16* __restrict__ qh, __nv_bfloat16* __restrict__ ql)
{
    int wid = threadIdx.x >> 5, lane = threadIdx.x & 31;
    int r = blockIdx.x * 8 + wid;
    float m = 0.0f;
    #pragma unroll
    for (int j = 0; j < 8; j++) m = fmaxf(m, pmax[(size_t)j * MM + r]);
    float rinv = 1.0f / (m + EPSV);
    #pragma unroll
    for (int j = 0; j < 8; j++) {
        int c = j * 128 + lane * 4;
        float4 a = *(const float4*)&z[(size_t)r * Cc + c];
        a.x *= rinv; a.y *= rinv; a.z *= rinv; a.w *= rinv;
        uint32_t h0, l0, h1, l1;
        split2(a.x, a.y, h0, l0);
        split2(a.z, a.w, h1, l1);
        *(uint2*)&qh[(size_t)r * Cc + c] = make_uint2(h0, h1);
        *(uint2*)&ql[(size_t)r * Cc + c] = make_uint2(l0, l1);
    }
}

// ---------------------------------------------------------------------------
// Prep kernels
// ---------------------------------------------------------------------------
__global__ void split_k(const float* __restrict__ s, __nv_bfloat16* __restrict__ h,
                        __nv_bfloat16* __restrict__ l, int n)
{
    for (int i = blockIdx.x * blockDim.x + threadIdx.x; i < n;
         i += gridDim.x * blockDim.x) {
        float x = s[i];
        __nv_bfloat16 hh = __float2bfloat16(x);
        h[i] = hh;
        l[i] = __float2bfloat16(x - __bfloat162float(hh));
    }
}
__global__ void tsplit_k(const float* __restrict__ W, __nv_bfloat16* __restrict__ Th,
                         __nv_bfloat16* __restrict__ Tl, int K, int N)
{
    for (int i = blockIdx.x * blockDim.x + threadIdx.x; i < K * N;
         i += gridDim.x * blockDim.x) {
        int k = i / N, n = i - k * N;
        float x = W[i];
        __nv_bfloat16 hh = __float2bfloat16(x);
        Th[(size_t)n * K + k] = hh;
        Tl[(size_t)n * K + k] = __float2bfloat16(x - __bfloat162float(hh));
    }
}
__global__ void mulsplit_k(const __nv_bfloat16* __restrict__ qh,
                           const __nv_bfloat16* __restrict__ ql,
                           const float* __restrict__ v,
                           __nv_bfloat16* __restrict__ ph,
                           __nv_bfloat16* __restrict__ pl, int n)
{
    for (int i = blockIdx.x * blockDim.x + threadIdx.x; i < n;
         i += gridDim.x * blockDim.x) {
        float x = (__bfloat162float(qh[i]) + __bfloat162float(ql[i])) * v[i];
        __nv_bfloat16 hh = __float2bfloat16(x);
        ph[i] = hh;
        pl[i] = __float2bfloat16(x - __bfloat162float(hh));
    }
}

// ---------------------------------------------------------------------------
extern "C" void kernel_launch(void* const* d_in, const int* in_sizes, int n_in,
                              void* d_out, int out_size)
{
    (void)in_sizes; (void)n_in; (void)out_size;
    const float* x        = (const float*)d_in[0];
    const float* attn_W   = (const float*)d_in[1];
    const float* attn_b   = (const float*)d_in[2];
    const float* freq_W   = (const float*)d_in[3];
    const float* freq_b   = (const float*)d_in[4];
    const float* out_W    = (const float*)d_in[5];
    const float* out_b    = (const float*)d_in[6];
    const float* proj_W   = (const float*)d_in[7];
    const float* proj_b   = (const float*)d_in[8];
    const float* identity = (const float*)d_in[9];

    __nv_bfloat16 *xh, *xl, *qh, *ql, *sch, *scl, *aWh, *aWl, *fWh, *fWl,
                  *oWh, *oWl, *pWh, *pWl, *idh, *idl;
    float *v, *z, *pmax;
    cudaGetSymbolAddress((void**)&xh,  g_xh);  cudaGetSymbolAddress((void**)&xl,  g_xl);
    cudaGetSymbolAddress((void**)&qh,  g_qh);  cudaGetSymbolAddress((void**)&ql,  g_ql);
    cudaGetSymbolAddress((void**)&v,   g_v);   cudaGetSymbolAddress((void**)&z,   g_z);
    cudaGetSymbolAddress((void**)&sch, g_sch); cudaGetSymbolAddress((void**)&scl, g_scl);
    cudaGetSymbolAddress((void**)&pmax,g_pmax);
    cudaGetSymbolAddress((void**)&aWh, g_aWh); cudaGetSymbolAddress((void**)&aWl, g_aWl);
    cudaGetSymbolAddress((void**)&fWh, g_fWh); cudaGetSymbolAddress((void**)&fWl, g_fWl);
    cudaGetSymbolAddress((void**)&oWh, g_oWh); cudaGetSymbolAddress((void**)&oWl, g_oWl);
    cudaGetSymbolAddress((void**)&pWh, g_pWh); cudaGetSymbolAddress((void**)&pWl, g_pWl);
    cudaGetSymbolAddress((void**)&idh, g_idh); cudaGetSymbolAddress((void**)&idl, g_idl);

    // smem: 3 stages * (128 + BN) rows * 80 B
    const int SM_BIG  = 3 * (128 + 128) * 80;   // 61440
    const int SM_FREQ = 3 * (128 + 64)  * 80;   // 46080
    cudaFuncSetAttribute(mma_gemm<0, 128, 1024>,
                         cudaFuncAttributeMaxDynamicSharedMemorySize, SM_BIG);
    cudaFuncSetAttribute(mma_gemm<1, 64, 2048>,
                         cudaFuncAttributeMaxDynamicSharedMemorySize, SM_FREQ);
    cudaFuncSetAttribute(mma_gemm<2, 128, 128>,
                         cudaFuncAttributeMaxDynamicSharedMemorySize, SM_BIG);
    cudaFuncSetAttribute(mma_gemm<3, 128, 1024>,
                         cudaFuncAttributeMaxDynamicSharedMemorySize, SM_BIG);

    // prep: split inputs / transpose+split weights
    split_k<<<8192, 256>>>(x, xh, xl, MM * Cc);
    split_k<<<4, 256>>>(identity, idh, idl, Cc);
    tsplit_k<<<2048, 256>>>(attn_W, aWh, aWl, 1024, 2048);
    tsplit_k<<<256, 256>>>(freq_W, fWh, fWl, 2048, 64);
    tsplit_k<<<256, 256>>>(out_W, oWh, oWl, 128, 1024);
    tsplit_k<<<1024, 256>>>(proj_W, pWh, pWl, 1024, 1024);

    // attn: qv = x @ attn_W + attn_b  -> q (bf16 hi/lo) | v (fp32)
    mma_gemm<0, 128, 1024><<<dim3(16, 128), 256, SM_BIG>>>(
        xh, xl, nullptr, nullptr, aWh, aWl, attn_b, v, qh, ql, nullptr, 0);

    // log-scan: 11 sequential steps
    for (int n = 1; n < Tt; n <<= 1) {
        mma_gemm<1, 64, 2048><<<dim3(1, 128), 256, SM_FREQ>>>(
            qh, ql, idh, idl, fWh, fWl, freq_b, nullptr, sch, scl, nullptr, n);
        mma_gemm<2, 128, 128><<<dim3(8, 128), 256, SM_BIG>>>(
            sch, scl, nullptr, nullptr, oWh, oWl, out_b, z,
            nullptr, nullptr, pmax, 0);
        normalize_kernel<<<MM / 8, 256>>>(z, pmax, qh, ql);
    }

    // proj: out = (q * v) @ proj_W + proj_b   (product precomputed into xh/xl)
    mulsplit_k<<<8192, 256>>>(qh, ql, v, xh, xl, MM * Cc);
    mma_gemm<3, 128, 1024><<<dim3(8, 128), 256, SM_BIG>>>(
        xh, xl, nullptr, nullptr, pWh, pWl, proj_b, (float*)d_out,
        nullptr, nullptr, nullptr, 0);
}

// round 6
// speedup vs baseline: 4.7671x; 1.2354x over previous
#include <cuda_runtime.h>
#include <cuda_bf16.h>
#include <math.h>
#include <stdint.h>

#define MM   16384
#define Cc   1024
#define Tt   2048
#define EPSV 1e-6f

// ---------------------------------------------------------------------------
// Scratch (__device__ globals; no allocation allowed)
// ---------------------------------------------------------------------------
__device__ __nv_bfloat16 g_xh[MM * Cc], g_xl[MM * Cc];
__device__ __nv_bfloat16 g_qh[MM * Cc], g_ql[MM * Cc];
__device__ float         g_v [MM * Cc];
__device__ float         g_z [MM * Cc];
__device__ __nv_bfloat16 g_sch[MM * 128], g_scl[MM * 128];
__device__ float         g_pmax[8 * MM];
__device__ __nv_bfloat16 g_aWh[2048 * 1024], g_aWl[2048 * 1024];
__device__ __nv_bfloat16 g_fWh[64 * 2048],   g_fWl[64 * 2048];
__device__ __nv_bfloat16 g_oWh[1024 * 128],  g_oWl[1024 * 128];
__device__ __nv_bfloat16 g_pWh[1024 * 1024], g_pWl[1024 * 1024];
__device__ __nv_bfloat16 g_idh[Cc], g_idl[Cc];

// ---------------------------------------------------------------------------
__device__ __forceinline__ uint32_t smem_u32(const void* p) {
    uint32_t a;
    asm("{ .reg .u64 t; cvta.to.shared.u64 t, %1; cvt.u32.u64 %0, t; }"
        : "=r"(a) : "l"(p));
    return a;
}
__device__ __forceinline__ void cp16(uint32_t dst, const void* src) {
    asm volatile("cp.async.cg.shared.global [%0], [%1], 16;"
                 :: "r"(dst), "l"(src));
}
#define CP_COMMIT() asm volatile("cp.async.commit_group;")
#define CP_WAIT1()  asm volatile("cp.async.wait_group 1;")
#define CP_WAIT0()  asm volatile("cp.async.wait_group 0;")

__device__ __forceinline__ void ldmA(uint32_t* a, uint32_t addr) {
    asm volatile("ldmatrix.sync.aligned.m8n8.x4.shared.b16 {%0,%1,%2,%3}, [%4];"
                 : "=r"(a[0]), "=r"(a[1]), "=r"(a[2]), "=r"(a[3]) : "r"(addr));
}
__device__ __forceinline__ void ldmB(uint32_t* b, uint32_t addr) {
    asm volatile("ldmatrix.sync.aligned.m8n8.x2.shared.b16 {%0,%1}, [%2];"
                 : "=r"(b[0]), "=r"(b[1]) : "r"(addr));
}
__device__ __forceinline__ void mma16816(float* c, const uint32_t* a,
                                         const uint32_t* b) {
    asm volatile("mma.sync.aligned.m16n8k16.row.col.f32.bf16.bf16.f32 "
                 "{%0,%1,%2,%3}, {%4,%5,%6,%7}, {%8,%9}, {%0,%1,%2,%3};"
                 : "+f"(c[0]), "+f"(c[1]), "+f"(c[2]), "+f"(c[3])
                 : "r"(a[0]), "r"(a[1]), "r"(a[2]), "r"(a[3]),
                   "r"(b[0]), "r"(b[1]));
}
__device__ __forceinline__ void split2(float a, float b, uint32_t& hi, uint32_t& lo) {
    __nv_bfloat16 ha = __float2bfloat16(a), hb = __float2bfloat16(b);
    __nv_bfloat162 hp = __halves2bfloat162(ha, hb);
    __nv_bfloat162 lp = __halves2bfloat162(
        __float2bfloat16(a - __bfloat162float(ha)),
        __float2bfloat16(b - __bfloat162float(hb)));
    hi = *(uint32_t*)&hp;
    lo = *(uint32_t*)&lp;
}

// ---------------------------------------------------------------------------
// Split-precision bf16 mma.sync GEMM, segment-fused k-loop.
// Per k-chunk the CTA stages Ah, Al, Bh, Bl tiles once and issues the three
// split products Ah*Bh + Ah*Bl + Al*Bh into one accumulator.
// B is pre-transposed [N][K].
// MODE 0: attn  (cols<1024 -> qh/ql bf16 split, else v fp32)
// MODE 1: freq  (A = [shift(q), q] folded into load; sincos -> sch/scl)
// MODE 2: out   (fp32 z + per-block row-max partials)
// MODE 3: proj  (plain fp32 out + bias)
// ---------------------------------------------------------------------------
template<int MODE, int BN, int KB>
__global__ __launch_bounds__(256)
void mma_gemm(const __nv_bfloat16* __restrict__ Ah, const __nv_bfloat16* __restrict__ Al,
              const __nv_bfloat16* __restrict__ idh, const __nv_bfloat16* __restrict__ idl,
              const __nv_bfloat16* __restrict__ Bh, const __nv_bfloat16* __restrict__ Bl,
              const float* __restrict__ bias,
              float* __restrict__ outf,
              __nv_bfloat16* __restrict__ outh, __nv_bfloat16* __restrict__ outl,
              float* __restrict__ pmax, int nShift)
{
    constexpr int BK     = 32;
    constexpr int STAGES = 3;
    constexpr int KT     = KB / BK;
    constexpr int LDS    = BK + 8;                 // halves, +16B pad
    constexpr int ROWB   = LDS * 2;                // 80 bytes / row
    constexpr int OFF_AL = 128 * ROWB;
    constexpr int OFF_BH = 256 * ROWB;
    constexpr int OFF_BL = (256 + BN) * ROWB;
    constexpr int STG    = (256 + 2 * BN) * ROWB;  // bytes per stage
    constexpr int WN     = BN / 4;                 // warp N extent
    constexpr int NI     = WN / 8;                 // n-tiles per warp

    extern __shared__ __align__(128) char smem[];
    const uint32_t sA = smem_u32(smem);

    const int tid  = threadIdx.x;
    const int wid  = tid >> 5, lane = tid & 31;
    const int wm   = wid >> 2, wn = wid & 3;       // 2 x 4 warp grid
    const int row0 = blockIdx.y * 128;
    const int n0   = blockIdx.x * BN;
    const int ALD  = (MODE == 2) ? 128 : Cc;       // A leading dim (elements)

    float acc[4][NI][4];
    #pragma unroll
    for (int mi = 0; mi < 4; mi++)
        #pragma unroll
        for (int ni = 0; ni < NI; ni++)
            #pragma unroll
            for (int r = 0; r < 4; r++) acc[mi][ni][r] = 0.0f;

    auto load_tiles = [&](int kt, int stage) {
        if (kt >= KT) return;
        const int kb    = kt * BK;
        const int chunk = tid & 3;                 // 4 x 16B per 32-half row
        const int kg    = kb + chunk * 8;
        const uint32_t stg = sA + stage * STG;
        #pragma unroll
        for (int p = 0; p < 2; p++) {
            const int row = (tid >> 2) + p * 64;
            const int rg  = row0 + row;
            const __nv_bfloat16 *srcH, *srcL;
            if (MODE == 1) {
                if (kg < Cc) {
                    int t = rg & (Tt - 1);
                    if (t >= nShift) {
                        size_t base = (size_t)(rg - nShift) * Cc + kg;
                        srcH = Ah + base; srcL = Al + base;
                    } else {
                        srcH = idh + kg; srcL = idl + kg;
                    }
                } else {
                    size_t base = (size_t)rg * Cc + (kg - Cc);
                    srcH = Ah + base; srcL = Al + base;
                }
            } else {
                size_t base = (size_t)rg * ALD + kg;
                srcH = Ah + base; srcL = Al + base;
            }
            const uint32_t so = (uint32_t)(row * LDS + chunk * 8) * 2;
            cp16(stg + so, srcH);
            cp16(stg + OFF_AL + so, srcL);
        }
        #pragma unroll
        for (int p = 0; p < BN / 64; p++) {
            const int row = (tid >> 2) + p * 64;   // n index
            const __nv_bfloat16* bo = (const __nv_bfloat16*)0 +
                                      ((size_t)(n0 + row) * KB + kg);
            const uint32_t so = (uint32_t)(row * LDS + chunk * 8) * 2;
            cp16(stg + OFF_BH + so, Bh + ((size_t)(n0 + row) * KB + kg));
            cp16(stg + OFF_BL + so, Bl + ((size_t)(n0 + row) * KB + kg));
            (void)bo;
        }
    };

    // prologue
    #pragma unroll
    for (int s = 0; s < STAGES - 1; s++) { load_tiles(s, s); CP_COMMIT(); }

    for (int kt = 0; kt < KT; kt++) {
        CP_WAIT1();
        __syncthreads();
        load_tiles(kt + STAGES - 1, (kt + STAGES - 1) % STAGES);
        CP_COMMIT();

        const uint32_t stg = sA + (kt % STAGES) * STG;
        #pragma unroll
        for (int ks = 0; ks < 2; ks++) {
            const uint32_t aoff = (uint32_t)(ks * 16 + (lane >> 4) * 8) * 2;
            const uint32_t boff = (uint32_t)(ks * 16 + ((lane >> 3) & 1) * 8) * 2;
            uint32_t afH[4][4];
            #pragma unroll
            for (int mi = 0; mi < 4; mi++)
                ldmA(afH[mi], stg +
                     (uint32_t)((wm * 64 + mi * 16 + (lane & 15)) * LDS) * 2 + aoff);
            uint32_t bfH[NI][2];
            #pragma unroll
            for (int ni = 0; ni < NI; ni++)
                ldmB(bfH[ni], stg + OFF_BH +
                     (uint32_t)((wn * WN + ni * 8 + (lane & 7)) * LDS) * 2 + boff);
            // Ah * Bh
            #pragma unroll
            for (int mi = 0; mi < 4; mi++)
                #pragma unroll
                for (int ni = 0; ni < NI; ni++)
                    mma16816(acc[mi][ni], afH[mi], bfH[ni]);
            // Al * Bh  (afL short-lived)
            {
                uint32_t afL[4][4];
                #pragma unroll
                for (int mi = 0; mi < 4; mi++)
                    ldmA(afL[mi], stg + OFF_AL +
                         (uint32_t)((wm * 64 + mi * 16 + (lane & 15)) * LDS) * 2 + aoff);
                #pragma unroll
                for (int mi = 0; mi < 4; mi++)
                    #pragma unroll
                    for (int ni = 0; ni < NI; ni++)
                        mma16816(acc[mi][ni], afL[mi], bfH[ni]);
            }
            // Ah * Bl  (bfL short-lived)
            {
                uint32_t bfL[NI][2];
                #pragma unroll
                for (int ni = 0; ni < NI; ni++)
                    ldmB(bfL[ni], stg + OFF_BL +
                         (uint32_t)((wn * WN + ni * 8 + (lane & 7)) * LDS) * 2 + boff);
                #pragma unroll
                for (int mi = 0; mi < 4; mi++)
                    #pragma unroll
                    for (int ni = 0; ni < NI; ni++)
                        mma16816(acc[mi][ni], afH[mi], bfL[ni]);
            }
        }
    }
    CP_WAIT0();
    __syncthreads();

    // ---- epilogue ----
    float* pm = (float*)smem;                      // [128][4] row-max partials
    float rmax[4][2];
    #pragma unroll
    for (int mi = 0; mi < 4; mi++) { rmax[mi][0] = 0.0f; rmax[mi][1] = 0.0f; }

    #pragma unroll
    for (int mi = 0; mi < 4; mi++) {
        const int R0 = row0 + wm * 64 + mi * 16 + (lane >> 2);
        const int R1 = R0 + 8;
        #pragma unroll
        for (int ni = 0; ni < NI; ni++) {
            const int c  = wn * WN + ni * 8 + 2 * (lane & 3);
            const int gc = n0 + c;
            const float b0 = bias[gc], b1 = bias[gc + 1];
            float v0 = acc[mi][ni][0] + b0, v1 = acc[mi][ni][1] + b1;
            float v2 = acc[mi][ni][2] + b0, v3 = acc[mi][ni][3] + b1;
            if (MODE == 0) {
                if (gc < Cc) {
                    uint32_t hi, lo;
                    split2(v0, v1, hi, lo);
                    *(uint32_t*)&outh[(size_t)R0 * Cc + gc] = hi;
                    *(uint32_t*)&outl[(size_t)R0 * Cc + gc] = lo;
                    split2(v2, v3, hi, lo);
                    *(uint32_t*)&outh[(size_t)R1 * Cc + gc] = hi;
                    *(uint32_t*)&outl[(size_t)R1 * Cc + gc] = lo;
                } else {
                    *(float2*)&outf[(size_t)R0 * Cc + gc - Cc] = make_float2(v0, v1);
                    *(float2*)&outf[(size_t)R1 * Cc + gc - Cc] = make_float2(v2, v3);
                }
            } else if (MODE == 1) {
                float s0, c0, s1, c1, s2, c2, s3, c3;
                sincosf(v0, &s0, &c0); sincosf(v1, &s1, &c1);
                sincosf(v2, &s2, &c2); sincosf(v3, &s3, &c3);
                uint32_t hi, lo;
                split2(s0, s1, hi, lo);
                *(uint32_t*)&outh[(size_t)R0 * 128 + gc] = hi;
                *(uint32_t*)&outl[(size_t)R0 * 128 + gc] = lo;
                split2(c0, c1, hi, lo);
                *(uint32_t*)&outh[(size_t)R0 * 128 + 64 + gc] = hi;
                *(uint32_t*)&outl[(size_t)R0 * 128 + 64 + gc] = lo;
                split2(s2, s3, hi, lo);
                *(uint32_t*)&outh[(size_t)R1 * 128 + gc] = hi;
                *(uint32_t*)&outl[(size_t)R1 * 128 + gc] = lo;
                split2(c2, c3, hi, lo);
                *(uint32_t*)&outh[(size_t)R1 * 128 + 64 + gc] = hi;
                *(uint32_t*)&outl[(size_t)R1 * 128 + 64 + gc] = lo;
            } else {
                *(float2*)&outf[(size_t)R0 * Cc + gc] = make_float2(v0, v1);
                *(float2*)&outf[(size_t)R1 * Cc + gc] = make_float2(v2, v3);
                if (MODE == 2) {
                    rmax[mi][0] = fmaxf(rmax[mi][0], fmaxf(fabsf(v0), fabsf(v1)));
                    rmax[mi][1] = fmaxf(rmax[mi][1], fmaxf(fabsf(v2), fabsf(v3)));
                }
            }
        }
    }

    if (MODE == 2) {
        #pragma unroll
        for (int mi = 0; mi < 4; mi++) {
            float m0 = rmax[mi][0], m1 = rmax[mi][1];
            #pragma unroll
            for (int off = 1; off < 4; off <<= 1) {
                m0 = fmaxf(m0, __shfl_xor_sync(0xffffffff, m0, off));
                m1 = fmaxf(m1, __shfl_xor_sync(0xffffffff, m1, off));
            }
            if ((lane & 3) == 0) {
                int lr = wm * 64 + mi * 16 + (lane >> 2);
                pm[lr * 4 + wn]       = m0;
                pm[(lr + 8) * 4 + wn] = m1;
            }
        }
        __syncthreads();
        if (tid < 128) {
            float m = fmaxf(fmaxf(pm[tid * 4], pm[tid * 4 + 1]),
                            fmaxf(pm[tid * 4 + 2], pm[tid * 4 + 3]));
            pmax[(size_t)blockIdx.x * MM + row0 + tid] = m;
        }
    }
}

// ---------------------------------------------------------------------------
// mmnorm finalize: q = z / (rowmax + eps), re-split into bf16 hi/lo.
// ---------------------------------------------------------------------------
__global__ __launch_bounds__(256)
void normalize_kernel(const float* __restrict__ z, const float* __restrict__ pmax,
                      __nv_bfloat16* __restrict__ qh, __nv_bfloat16* __restrict__ ql)
{
    int wid = threadIdx.x >> 5, lane = threadIdx.x & 31;
    int r = blockIdx.x * 8 + wid;
    float m = 0.0f;
    #pragma unroll
    for (int j = 0; j < 8; j++) m = fmaxf(m, pmax[(size_t)j * MM + r]);
    float rinv = 1.0f / (m + EPSV);
    #pragma unroll
    for (int j = 0; j < 8; j++) {
        int c = j * 128 + lane * 4;
        float4 a = *(const float4*)&z[(size_t)r * Cc + c];
        a.x *= rinv; a.y *= rinv; a.z *= rinv; a.w *= rinv;
        uint32_t h0, l0, h1, l1;
        split2(a.x, a.y, h0, l0);
        split2(a.z, a.w, h1, l1);
        *(uint2*)&qh[(size_t)r * Cc + c] = make_uint2(h0, h1);
        *(uint2*)&ql[(size_t)r * Cc + c] = make_uint2(l0, l1);
    }
}

// ---------------------------------------------------------------------------
// Prep kernels
// ---------------------------------------------------------------------------
__global__ void split_k(const float* __restrict__ s, __nv_bfloat16* __restrict__ h,
                        __nv_bfloat16* __restrict__ l, int n)
{
    for (int i = blockIdx.x * blockDim.x + threadIdx.x; i < n;
         i += gridDim.x * blockDim.x) {
        float x = s[i];
        __nv_bfloat16 hh = __float2bfloat16(x);
        h[i] = hh;
        l[i] = __float2bfloat16(x - __bfloat162float(hh));
    }
}
__global__ void tsplit_k(const float* __restrict__ W, __nv_bfloat16* __restrict__ Th,
                         __nv_bfloat16* __restrict__ Tl, int K, int N)
{
    for (int i = blockIdx.x * blockDim.x + threadIdx.x; i < K * N;
         i += gridDim.x * blockDim.x) {
        int k = i / N, n = i - k * N;
        float x = W[i];
        __nv_bfloat16 hh = __float2bfloat16(x);
        Th[(size_t)n * K + k] = hh;
        Tl[(size_t)n * K + k] = __float2bfloat16(x - __bfloat162float(hh));
    }
}
__global__ void mulsplit_k(const __nv_bfloat16* __restrict__ qh,
                           const __nv_bfloat16* __restrict__ ql,
                           const float* __restrict__ v,
                           __nv_bfloat16* __restrict__ ph,
                           __nv_bfloat16* __restrict__ pl, int n)
{
    for (int i = blockIdx.x * blockDim.x + threadIdx.x; i < n;
         i += gridDim.x * blockDim.x) {
        float x = (__bfloat162float(qh[i]) + __bfloat162float(ql[i])) * v[i];
        __nv_bfloat16 hh = __float2bfloat16(x);
        ph[i] = hh;
        pl[i] = __float2bfloat16(x - __bfloat162float(hh));
    }
}

// ---------------------------------------------------------------------------
extern "C" void kernel_launch(void* const* d_in, const int* in_sizes, int n_in,
                              void* d_out, int out_size)
{
    (void)in_sizes; (void)n_in; (void)out_size;
    const float* x        = (const float*)d_in[0];
    const float* attn_W   = (const float*)d_in[1];
    const float* attn_b   = (const float*)d_in[2];
    const float* freq_W   = (const float*)d_in[3];
    const float* freq_b   = (const float*)d_in[4];
    const float* out_W    = (const float*)d_in[5];
    const float* out_b    = (const float*)d_in[6];
    const float* proj_W   = (const float*)d_in[7];
    const float* proj_b   = (const float*)d_in[8];
    const float* identity = (const float*)d_in[9];

    __nv_bfloat16 *xh, *xl, *qh, *ql, *sch, *scl, *aWh, *aWl, *fWh, *fWl,
                  *oWh, *oWl, *pWh, *pWl, *idh, *idl;
    float *v, *z, *pmax;
    cudaGetSymbolAddress((void**)&xh,  g_xh);  cudaGetSymbolAddress((void**)&xl,  g_xl);
    cudaGetSymbolAddress((void**)&qh,  g_qh);  cudaGetSymbolAddress((void**)&ql,  g_ql);
    cudaGetSymbolAddress((void**)&v,   g_v);   cudaGetSymbolAddress((void**)&z,   g_z);
    cudaGetSymbolAddress((void**)&sch, g_sch); cudaGetSymbolAddress((void**)&scl, g_scl);
    cudaGetSymbolAddress((void**)&pmax,g_pmax);
    cudaGetSymbolAddress((void**)&aWh, g_aWh); cudaGetSymbolAddress((void**)&aWl, g_aWl);
    cudaGetSymbolAddress((void**)&fWh, g_fWh); cudaGetSymbolAddress((void**)&fWl, g_fWl);
    cudaGetSymbolAddress((void**)&oWh, g_oWh); cudaGetSymbolAddress((void**)&oWl, g_oWl);
    cudaGetSymbolAddress((void**)&pWh, g_pWh); cudaGetSymbolAddress((void**)&pWl, g_pWl);
    cudaGetSymbolAddress((void**)&idh, g_idh); cudaGetSymbolAddress((void**)&idl, g_idl);

    // smem: 3 stages * (256 + 2*BN) rows * 80 B
    const int SM_BIG  = 3 * (256 + 256) * 80;   // 122880
    const int SM_FREQ = 3 * (256 + 128) * 80;   // 92160
    cudaFuncSetAttribute(mma_gemm<0, 128, 1024>,
                         cudaFuncAttributeMaxDynamicSharedMemorySize, SM_BIG);
    cudaFuncSetAttribute(mma_gemm<1, 64, 2048>,
                         cudaFuncAttributeMaxDynamicSharedMemorySize, SM_FREQ);
    cudaFuncSetAttribute(mma_gemm<2, 128, 128>,
                         cudaFuncAttributeMaxDynamicSharedMemorySize, SM_BIG);
    cudaFuncSetAttribute(mma_gemm<3, 128, 1024>,
                         cudaFuncAttributeMaxDynamicSharedMemorySize, SM_BIG);

    // prep: split inputs / transpose+split weights
    split_k<<<8192, 256>>>(x, xh, xl, MM * Cc);
    split_k<<<4, 256>>>(identity, idh, idl, Cc);
    tsplit_k<<<2048, 256>>>(attn_W, aWh, aWl, 1024, 2048);
    tsplit_k<<<256, 256>>>(freq_W, fWh, fWl, 2048, 64);
    tsplit_k<<<256, 256>>>(out_W, oWh, oWl, 128, 1024);
    tsplit_k<<<1024, 256>>>(proj_W, pWh, pWl, 1024, 1024);

    // attn: qv = x @ attn_W + attn_b  -> q (bf16 hi/lo) | v (fp32)
    mma_gemm<0, 128, 1024><<<dim3(16, 128), 256, SM_BIG>>>(
        xh, xl, nullptr, nullptr, aWh, aWl, attn_b, v, qh, ql, nullptr, 0);

    // log-scan: 11 sequential steps
    for (int n = 1; n < Tt; n <<= 1) {
        mma_gemm<1, 64, 2048><<<dim3(1, 128), 256, SM_FREQ>>>(
            qh, ql, idh, idl, fWh, fWl, freq_b, nullptr, sch, scl, nullptr, n);
        mma_gemm<2, 128, 128><<<dim3(8, 128), 256, SM_BIG>>>(
            sch, scl, nullptr, nullptr, oWh, oWl, out_b, z,
            nullptr, nullptr, pmax, 0);
        normalize_kernel<<<MM / 8, 256>>>(z, pmax, qh, ql);
    }

    // proj: out = (q * v) @ proj_W + proj_b   (product precomputed into xh/xl)
    mulsplit_k<<<8192, 256>>>(qh, ql, v, xh, xl, MM * Cc);
    mma_gemm<3, 128, 1024><<<dim3(8, 128), 256, SM_BIG>>>(
        xh, xl, nullptr, nullptr, pWh, pWl, proj_b, (float*)d_out,
        nullptr, nullptr, nullptr, 0);
}

// round 7
// speedup vs baseline: 8.0214x; 1.6827x over previous
#include <cuda_runtime.h>
#include <cuda_fp16.h>
#include <math.h>
#include <stdint.h>

#define MM   16384
#define Cc   1024
#define Tt   2048
#define EPSV 1e-6f

// ---------------------------------------------------------------------------
// Scratch (__device__ globals; no allocation allowed)
// ---------------------------------------------------------------------------
__device__ __half g_xh[MM * Cc], g_xl[MM * Cc];   // x split; reused for q*v
__device__ __half g_zh[MM * Cc], g_zl[MM * Cc];   // scan state (unnormalized z)
__device__ float  g_v [MM * Cc];
__device__ float  g_u [MM * 128];                 // U = z @ [W1|W2]
__device__ __half g_sch[MM * 128], g_scl[MM * 128];
__device__ float  g_pmax[8 * MM];
__device__ float  g_c1[64];
__device__ float  g_zero[2048];                   // zero bias (static init 0)
__device__ __half g_aW[2048 * 1024];              // attn_W^T  [N][K]
__device__ __half g_fW[128 * 1024];               // [W1|W2]^T [N][K]
__device__ __half g_oW[1024 * 128];               // out_W^T   [N][K]
__device__ __half g_pW[1024 * 1024];              // proj_W^T  [N][K]

// ---------------------------------------------------------------------------
__device__ __forceinline__ uint32_t smem_u32(const void* p) {
    uint32_t a;
    asm("{ .reg .u64 t; cvta.to.shared.u64 t, %1; cvt.u32.u64 %0, t; }"
        : "=r"(a) : "l"(p));
    return a;
}
__device__ __forceinline__ void cp16(uint32_t dst, const void* src) {
    asm volatile("cp.async.cg.shared.global [%0], [%1], 16;"
                 :: "r"(dst), "l"(src));
}
#define CP_COMMIT() asm volatile("cp.async.commit_group;")
#define CP_WAIT1()  asm volatile("cp.async.wait_group 1;")
#define CP_WAIT0()  asm volatile("cp.async.wait_group 0;")

__device__ __forceinline__ void ldmA(uint32_t* a, uint32_t addr) {
    asm volatile("ldmatrix.sync.aligned.m8n8.x4.shared.b16 {%0,%1,%2,%3}, [%4];"
                 : "=r"(a[0]), "=r"(a[1]), "=r"(a[2]), "=r"(a[3]) : "r"(addr));
}
__device__ __forceinline__ void ldmB(uint32_t* b, uint32_t addr) {
    asm volatile("ldmatrix.sync.aligned.m8n8.x2.shared.b16 {%0,%1}, [%2];"
                 : "=r"(b[0]), "=r"(b[1]) : "r"(addr));
}
__device__ __forceinline__ void mma16816(float* c, const uint32_t* a,
                                         const uint32_t* b) {
    asm volatile("mma.sync.aligned.m16n8k16.row.col.f32.f16.f16.f32 "
                 "{%0,%1,%2,%3}, {%4,%5,%6,%7}, {%8,%9}, {%0,%1,%2,%3};"
                 : "+f"(c[0]), "+f"(c[1]), "+f"(c[2]), "+f"(c[3])
                 : "r"(a[0]), "r"(a[1]), "r"(a[2]), "r"(a[3]),
                   "r"(b[0]), "r"(b[1]));
}
__device__ __forceinline__ void splitH2(float a, float b, uint32_t& hi, uint32_t& lo) {
    __half ha = __float2half_rn(a), hb = __float2half_rn(b);
    __half2 hp = __halves2half2(ha, hb);
    __half2 lp = __halves2half2(__float2half_rn(a - __half2float(ha)),
                                __float2half_rn(b - __half2float(hb)));
    hi = *(uint32_t*)&hp;
    lo = *(uint32_t*)&lp;
}
__device__ __forceinline__ float get_rinv(const float* pmax, int r) {
    if (pmax == nullptr) return 1.0f;
    float m = 0.0f;
    #pragma unroll
    for (int j = 0; j < 8; j++) m = fmaxf(m, pmax[j * MM + r]);
    return 1.0f / (m + EPSV);
}

// ---------------------------------------------------------------------------
// 2-term fp16 split GEMM: D = (Ah+Al) @ B^T (+bias).  BM=128, BN=128.
// A exact (hi+lo fp16); B rounded to fp16 (residual ~2^-12, dropped).
// EPI 0: attn (gc<1024 -> zh/zl split, else v fp32)
// EPI 1: fp32 out + bias (freq-U, proj)
// EPI 2: split zh/zl + per-block row-max partials (out step)
// ---------------------------------------------------------------------------
template<int EPI, int KB, int ALD, int NOUT>
__global__ __launch_bounds__(256, 2)
void mma_gemm(const __half* __restrict__ Ah, const __half* __restrict__ Al,
              const __half* __restrict__ B,
              const float* __restrict__ bias,
              float* __restrict__ outf,
              __half* __restrict__ outh, __half* __restrict__ outl,
              float* __restrict__ pmax)
{
    constexpr int BN     = 128;
    constexpr int BK     = 32;
    constexpr int STAGES = 3;
    constexpr int KT     = KB / BK;
    constexpr int LDS    = BK + 8;                 // halves, +16B pad
    constexpr int ROWB   = LDS * 2;                // 80 B/row
    constexpr int OFF_AL = 128 * ROWB;
    constexpr int OFF_B  = 256 * ROWB;
    constexpr int STG    = (256 + BN) * ROWB;      // 30720 B / stage
    constexpr int NI     = 4;                      // (BN/4)/8

    extern __shared__ __align__(128) char smem[];
    const uint32_t sA = smem_u32(smem);

    const int tid  = threadIdx.x;
    const int wid  = tid >> 5, lane = tid & 31;
    const int wm   = wid >> 2, wn = wid & 3;
    const int row0 = blockIdx.y * 128;
    const int n0   = blockIdx.x * BN;

    float acc[4][NI][4];
    #pragma unroll
    for (int mi = 0; mi < 4; mi++)
        #pragma unroll
        for (int ni = 0; ni < NI; ni++)
            #pragma unroll
            for (int r = 0; r < 4; r++) acc[mi][ni][r] = 0.0f;

    auto load_tiles = [&](int kt, int stage) {
        if (kt >= KT) return;
        const int chunk = tid & 3;
        const int kg    = kt * BK + chunk * 8;
        const uint32_t stg = sA + stage * STG;
        #pragma unroll
        for (int p = 0; p < 2; p++) {
            const int row = (tid >> 2) + p * 64;
            const size_t base = (size_t)(row0 + row) * ALD + kg;
            const uint32_t so = (uint32_t)(row * LDS + chunk * 8) * 2;
            cp16(stg + so, Ah + base);
            cp16(stg + OFF_AL + so, Al + base);
        }
        #pragma unroll
        for (int p = 0; p < 2; p++) {
            const int row = (tid >> 2) + p * 64;
            const uint32_t so = (uint32_t)(row * LDS + chunk * 8) * 2;
            cp16(stg + OFF_B + so, B + ((size_t)(n0 + row) * KB + kg));
        }
    };

    #pragma unroll
    for (int s = 0; s < STAGES - 1; s++) { load_tiles(s, s); CP_COMMIT(); }

    for (int kt = 0; kt < KT; kt++) {
        CP_WAIT1();
        __syncthreads();
        load_tiles(kt + STAGES - 1, (kt + STAGES - 1) % STAGES);
        CP_COMMIT();

        const uint32_t stg = sA + (kt % STAGES) * STG;
        #pragma unroll
        for (int ks = 0; ks < 2; ks++) {
            const uint32_t aoff = (uint32_t)(ks * 16 + (lane >> 4) * 8) * 2;
            const uint32_t boff = (uint32_t)(ks * 16 + ((lane >> 3) & 1) * 8) * 2;
            uint32_t bfH[NI][2];
            #pragma unroll
            for (int ni = 0; ni < NI; ni++)
                ldmB(bfH[ni], stg + OFF_B +
                     (uint32_t)((wn * 32 + ni * 8 + (lane & 7)) * LDS) * 2 + boff);
            uint32_t afH[4][4];
            #pragma unroll
            for (int mi = 0; mi < 4; mi++)
                ldmA(afH[mi], stg +
                     (uint32_t)((wm * 64 + mi * 16 + (lane & 15)) * LDS) * 2 + aoff);
            #pragma unroll
            for (int mi = 0; mi < 4; mi++)
                #pragma unroll
                for (int ni = 0; ni < NI; ni++)
                    mma16816(acc[mi][ni], afH[mi], bfH[ni]);
            uint32_t afL[4][4];
            #pragma unroll
            for (int mi = 0; mi < 4; mi++)
                ldmA(afL[mi], stg + OFF_AL +
                     (uint32_t)((wm * 64 + mi * 16 + (lane & 15)) * LDS) * 2 + aoff);
            #pragma unroll
            for (int mi = 0; mi < 4; mi++)
                #pragma unroll
                for (int ni = 0; ni < NI; ni++)
                    mma16816(acc[mi][ni], afL[mi], bfH[ni]);
        }
    }
    CP_WAIT0();
    __syncthreads();

    // ---- epilogue ----
    float* pm = (float*)smem;
    float rmax[4][2];
    #pragma unroll
    for (int mi = 0; mi < 4; mi++) { rmax[mi][0] = 0.0f; rmax[mi][1] = 0.0f; }

    #pragma unroll
    for (int mi = 0; mi < 4; mi++) {
        const int R0 = row0 + wm * 64 + mi * 16 + (lane >> 2);
        const int R1 = R0 + 8;
        #pragma unroll
        for (int ni = 0; ni < NI; ni++) {
            const int gc = n0 + wn * 32 + ni * 8 + 2 * (lane & 3);
            const float b0 = bias[gc], b1 = bias[gc + 1];
            float v0 = acc[mi][ni][0] + b0, v1 = acc[mi][ni][1] + b1;
            float v2 = acc[mi][ni][2] + b0, v3 = acc[mi][ni][3] + b1;
            if (EPI == 0) {
                if (gc < Cc) {
                    uint32_t hi, lo;
                    splitH2(v0, v1, hi, lo);
                    *(uint32_t*)&outh[(size_t)R0 * Cc + gc] = hi;
                    *(uint32_t*)&outl[(size_t)R0 * Cc + gc] = lo;
                    splitH2(v2, v3, hi, lo);
                    *(uint32_t*)&outh[(size_t)R1 * Cc + gc] = hi;
                    *(uint32_t*)&outl[(size_t)R1 * Cc + gc] = lo;
                } else {
                    *(float2*)&outf[(size_t)R0 * Cc + gc - Cc] = make_float2(v0, v1);
                    *(float2*)&outf[(size_t)R1 * Cc + gc - Cc] = make_float2(v2, v3);
                }
            } else if (EPI == 1) {
                *(float2*)&outf[(size_t)R0 * NOUT + gc] = make_float2(v0, v1);
                *(float2*)&outf[(size_t)R1 * NOUT + gc] = make_float2(v2, v3);
            } else {
                uint32_t hi, lo;
                splitH2(v0, v1, hi, lo);
                *(uint32_t*)&outh[(size_t)R0 * NOUT + gc] = hi;
                *(uint32_t*)&outl[(size_t)R0 * NOUT + gc] = lo;
                splitH2(v2, v3, hi, lo);
                *(uint32_t*)&outh[(size_t)R1 * NOUT + gc] = hi;
                *(uint32_t*)&outl[(size_t)R1 * NOUT + gc] = lo;
                rmax[mi][0] = fmaxf(rmax[mi][0], fmaxf(fabsf(v0), fabsf(v1)));
                rmax[mi][1] = fmaxf(rmax[mi][1], fmaxf(fabsf(v2), fabsf(v3)));
            }
        }
    }

    if (EPI == 2) {
        #pragma unroll
        for (int mi = 0; mi < 4; mi++) {
            float m0 = rmax[mi][0], m1 = rmax[mi][1];
            #pragma unroll
            for (int off = 1; off < 4; off <<= 1) {
                m0 = fmaxf(m0, __shfl_xor_sync(0xffffffff, m0, off));
                m1 = fmaxf(m1, __shfl_xor_sync(0xffffffff, m1, off));
            }
            if ((lane & 3) == 0) {
                int lr = wm * 64 + mi * 16 + (lane >> 2);
                pm[lr * 4 + wn]       = m0;
                pm[(lr + 8) * 4 + wn] = m1;
            }
        }
        __syncthreads();
        if (tid < 128) {
            float m = fmaxf(fmaxf(pm[tid * 4], pm[tid * 4 + 1]),
                            fmaxf(pm[tid * 4 + 2], pm[tid * 4 + 3]));
            pmax[(size_t)blockIdx.x * MM + row0 + tid] = m;
        }
    }
}

// ---------------------------------------------------------------------------
// combine: f = rinv[t-n]*U1[t-n] (or c1) + rinv[t]*U2[t] + freq_b
//          sc = [sin f, cos f] split to fp16 hi/lo
// ---------------------------------------------------------------------------
__global__ __launch_bounds__(256)
void combine_k(const float* __restrict__ U, const float* __restrict__ pmax,
               const float* __restrict__ c1, const float* __restrict__ freq_b,
               __half* __restrict__ sch, __half* __restrict__ scl, int nShift)
{
    const int n   = threadIdx.x & 63;
    const int row = blockIdx.x * 4 + (threadIdx.x >> 6);
    const int t   = row & (Tt - 1);

    float u2 = U[(size_t)row * 128 + 64 + n] * get_rinv(pmax, row);
    float u1;
    if (t >= nShift) {
        int rp = row - nShift;
        u1 = U[(size_t)rp * 128 + n] * get_rinv(pmax, rp);
    } else {
        u1 = c1[n];
    }
    float f = u1 + u2 + freq_b[n];
    float s, c;
    sincosf(f, &s, &c);
    __half sh = __float2half_rn(s), ch = __float2half_rn(c);
    sch[(size_t)row * 128 + n]      = sh;
    scl[(size_t)row * 128 + n]      = __float2half_rn(s - __half2float(sh));
    sch[(size_t)row * 128 + 64 + n] = ch;
    scl[(size_t)row * 128 + 64 + n] = __float2half_rn(c - __half2float(ch));
}

// ---------------------------------------------------------------------------
// Prep kernels
// ---------------------------------------------------------------------------
__global__ void split_k(const float* __restrict__ s, __half* __restrict__ h,
                        __half* __restrict__ l, int n)
{
    for (int i = blockIdx.x * blockDim.x + threadIdx.x; i < n;
         i += gridDim.x * blockDim.x) {
        float x = s[i];
        __half hh = __float2half_rn(x);
        h[i] = hh;
        l[i] = __float2half_rn(x - __half2float(hh));
    }
}
__global__ void tsplit_h(const float* __restrict__ W, __half* __restrict__ Th,
                         int K, int N)
{
    for (int i = blockIdx.x * blockDim.x + threadIdx.x; i < K * N;
         i += gridDim.x * blockDim.x) {
        int k = i / N, n = i - k * N;
        Th[(size_t)n * K + k] = __float2half_rn(W[i]);
    }
}
__global__ void fwt_k(const float* __restrict__ freq_W, __half* __restrict__ fW)
{
    for (int i = blockIdx.x * blockDim.x + threadIdx.x; i < 128 * 1024;
         i += gridDim.x * blockDim.x) {
        int n = i >> 10, k = i & 1023;
        float w = (n < 64) ? freq_W[(size_t)k * 64 + n]
                           : freq_W[(size_t)(1024 + k) * 64 + (n - 64)];
        fW[i] = __float2half_rn(w);
    }
}
__global__ void c1_k(const float* __restrict__ freq_W,
                     const float* __restrict__ identity, float* __restrict__ c1)
{
    __shared__ float red[256];
    const int n = blockIdx.x;
    float s = 0.0f;
    for (int k = threadIdx.x; k < 1024; k += 256)
        s += identity[k] * freq_W[(size_t)k * 64 + n];
    red[threadIdx.x] = s;
    __syncthreads();
    for (int o = 128; o > 0; o >>= 1) {
        if (threadIdx.x < o) red[threadIdx.x] += red[threadIdx.x + o];
        __syncthreads();
    }
    if (threadIdx.x == 0) c1[n] = red[0];
}
// p = (zh+zl)*rinv*v split to fp16 hi/lo (for proj A)
__global__ __launch_bounds__(256)
void mulsplit_k(const __half* __restrict__ zh, const __half* __restrict__ zl,
                const float* __restrict__ pmax, const float* __restrict__ v,
                __half* __restrict__ ph, __half* __restrict__ pl)
{
    int wid = threadIdx.x >> 5, lane = threadIdx.x & 31;
    int r = blockIdx.x * 8 + wid;
    float rinv = get_rinv(pmax, r);
    #pragma unroll
    for (int j = 0; j < 8; j++) {
        int c = j * 128 + lane * 4;
        size_t b = (size_t)r * Cc + c;
        uint2 hw = *(const uint2*)&zh[b];
        uint2 lw = *(const uint2*)&zl[b];
        float4 vv = *(const float4*)&v[b];
        __half2 h0 = *(__half2*)&hw.x, h1 = *(__half2*)&hw.y;
        __half2 l0 = *(__half2*)&lw.x, l1 = *(__half2*)&lw.y;
        float2 f0 = __half22float2(h0), f1 = __half22float2(h1);
        float2 g0 = __half22float2(l0), g1 = __half22float2(l1);
        float p0 = (f0.x + g0.x) * rinv * vv.x;
        float p1 = (f0.y + g0.y) * rinv * vv.y;
        float p2 = (f1.x + g1.x) * rinv * vv.z;
        float p3 = (f1.y + g1.y) * rinv * vv.w;
        uint32_t hA, lA, hB, lB;
        splitH2(p0, p1, hA, lA);
        splitH2(p2, p3, hB, lB);
        *(uint2*)&ph[b] = make_uint2(hA, hB);
        *(uint2*)&pl[b] = make_uint2(lA, lB);
    }
}

// ---------------------------------------------------------------------------
extern "C" void kernel_launch(void* const* d_in, const int* in_sizes, int n_in,
                              void* d_out, int out_size)
{
    (void)in_sizes; (void)n_in; (void)out_size;
    const float* x        = (const float*)d_in[0];
    const float* attn_W   = (const float*)d_in[1];
    const float* attn_b   = (const float*)d_in[2];
    const float* freq_W   = (const float*)d_in[3];
    const float* freq_b   = (const float*)d_in[4];
    const float* out_W    = (const float*)d_in[5];
    const float* out_b    = (const float*)d_in[6];
    const float* proj_W   = (const float*)d_in[7];
    const float* proj_b   = (const float*)d_in[8];
    const float* identity = (const float*)d_in[9];

    __half *xh, *xl, *zh, *zl, *sch, *scl, *aW, *fW, *oW, *pW;
    float *v, *u, *pmax, *c1, *zerob;
    cudaGetSymbolAddress((void**)&xh,  g_xh);  cudaGetSymbolAddress((void**)&xl,  g_xl);
    cudaGetSymbolAddress((void**)&zh,  g_zh);  cudaGetSymbolAddress((void**)&zl,  g_zl);
    cudaGetSymbolAddress((void**)&v,   g_v);   cudaGetSymbolAddress((void**)&u,   g_u);
    cudaGetSymbolAddress((void**)&sch, g_sch); cudaGetSymbolAddress((void**)&scl, g_scl);
    cudaGetSymbolAddress((void**)&pmax,g_pmax);cudaGetSymbolAddress((void**)&c1,  g_c1);
    cudaGetSymbolAddress((void**)&zerob, g_zero);
    cudaGetSymbolAddress((void**)&aW,  g_aW);  cudaGetSymbolAddress((void**)&fW,  g_fW);
    cudaGetSymbolAddress((void**)&oW,  g_oW);  cudaGetSymbolAddress((void**)&pW,  g_pW);

    const int SMB = 3 * (256 + 128) * 80;   // 92160
    cudaFuncSetAttribute(mma_gemm<0, 1024, 1024, 2048>,
                         cudaFuncAttributeMaxDynamicSharedMemorySize, SMB);
    cudaFuncSetAttribute(mma_gemm<1, 1024, 1024, 128>,
                         cudaFuncAttributeMaxDynamicSharedMemorySize, SMB);
    cudaFuncSetAttribute(mma_gemm<2, 128, 128, 1024>,
                         cudaFuncAttributeMaxDynamicSharedMemorySize, SMB);
    cudaFuncSetAttribute(mma_gemm<1, 1024, 1024, 1024>,
                         cudaFuncAttributeMaxDynamicSharedMemorySize, SMB);

    // prep
    split_k<<<8192, 256>>>(x, xh, xl, MM * Cc);
    tsplit_h<<<2048, 256>>>(attn_W, aW, 1024, 2048);
    fwt_k<<<256, 256>>>(freq_W, fW);
    tsplit_h<<<256, 256>>>(out_W, oW, 128, 1024);
    tsplit_h<<<1024, 256>>>(proj_W, pW, 1024, 1024);
    c1_k<<<64, 256>>>(freq_W, identity, c1);

    // attn: qv = x @ attn_W + attn_b -> q (zh/zl fp16 split) | v (fp32)
    mma_gemm<0, 1024, 1024, 2048><<<dim3(16, 128), 256, SMB>>>(
        xh, xl, aW, attn_b, v, zh, zl, nullptr);

    // log-scan
    int iter = 0;
    for (int n = 1; n < Tt; n <<= 1, iter++) {
        mma_gemm<1, 1024, 1024, 128><<<dim3(1, 128), 256, SMB>>>(
            zh, zl, fW, zerob, u, nullptr, nullptr, nullptr);
        combine_k<<<MM / 4, 256>>>(u, (iter == 0) ? nullptr : pmax,
                                   c1, freq_b, sch, scl, n);
        mma_gemm<2, 128, 128, 1024><<<dim3(8, 128), 256, SMB>>>(
            sch, scl, oW, out_b, nullptr, zh, zl, pmax);
    }

    // proj: out = (mmnorm(z) * v) @ proj_W + proj_b
    mulsplit_k<<<MM / 8, 256>>>(zh, zl, pmax, v, xh, xl);
    mma_gemm<1, 1024, 1024, 1024><<<dim3(8, 128), 256, SMB>>>(
        xh, xl, pW, proj_b, (float*)d_out, nullptr, nullptr, nullptr);
}

// round 8
// speedup vs baseline: 9.4435x; 1.1773x over previous
#include <cuda_runtime.h>
#include <cuda_fp16.h>
#include <math.h>
#include <stdint.h>

#define MM   16384
#define Cc   1024
#define Tt   2048
#define EPSV 1e-6f

// ---------------------------------------------------------------------------
// Scratch (__device__ globals; no allocation allowed)
// ---------------------------------------------------------------------------
__device__ __half g_xh[MM * Cc];                  // x fp16; reused for q*v
__device__ __half g_zh[MM * Cc], g_zl[MM * Cc];   // scan state (unnormalized z)
__device__ float  g_v [MM * Cc];
__device__ float  g_u [MM * 128];                 // U = z @ [W1|W2]
__device__ __half g_sch[MM * 128], g_scl[MM * 128];
__device__ float  g_pmax[8 * MM];
__device__ float  g_c1[64];
__device__ float  g_zero[2048];                   // zero bias (static init 0)
__device__ __half g_aW[2048 * 1024];              // attn_W^T  [N][K]
__device__ __half g_fW[128 * 1024];               // [W1|W2]^T [N][K]
__device__ __half g_oW[1024 * 128];               // out_W^T   [N][K]
__device__ __half g_pW[1024 * 1024];              // proj_W^T  [N][K]

// ---------------------------------------------------------------------------
__device__ __forceinline__ uint32_t smem_u32(const void* p) {
    uint32_t a;
    asm("{ .reg .u64 t; cvta.to.shared.u64 t, %1; cvt.u32.u64 %0, t; }"
        : "=r"(a) : "l"(p));
    return a;
}
__device__ __forceinline__ void cp16(uint32_t dst, const void* src) {
    asm volatile("cp.async.cg.shared.global [%0], [%1], 16;"
                 :: "r"(dst), "l"(src));
}
#define CP_COMMIT() asm volatile("cp.async.commit_group;")
#define CP_WAIT1()  asm volatile("cp.async.wait_group 1;")
#define CP_WAIT0()  asm volatile("cp.async.wait_group 0;")

__device__ __forceinline__ void ldmA(uint32_t* a, uint32_t addr) {
    asm volatile("ldmatrix.sync.aligned.m8n8.x4.shared.b16 {%0,%1,%2,%3}, [%4];"
                 : "=r"(a[0]), "=r"(a[1]), "=r"(a[2]), "=r"(a[3]) : "r"(addr));
}
__device__ __forceinline__ void ldmB(uint32_t* b, uint32_t addr) {
    asm volatile("ldmatrix.sync.aligned.m8n8.x2.shared.b16 {%0,%1}, [%2];"
                 : "=r"(b[0]), "=r"(b[1]) : "r"(addr));
}
__device__ __forceinline__ void mma16816(float* c, const uint32_t* a,
                                         const uint32_t* b) {
    asm volatile("mma.sync.aligned.m16n8k16.row.col.f32.f16.f16.f32 "
                 "{%0,%1,%2,%3}, {%4,%5,%6,%7}, {%8,%9}, {%0,%1,%2,%3};"
                 : "+f"(c[0]), "+f"(c[1]), "+f"(c[2]), "+f"(c[3])
                 : "r"(a[0]), "r"(a[1]), "r"(a[2]), "r"(a[3]),
                   "r"(b[0]), "r"(b[1]));
}
__device__ __forceinline__ void splitH2(float a, float b, uint32_t& hi, uint32_t& lo) {
    __half ha = __float2half_rn(a), hb = __float2half_rn(b);
    __half2 hp = __halves2half2(ha, hb);
    __half2 lp = __halves2half2(__float2half_rn(a - __half2float(ha)),
                                __float2half_rn(b - __half2float(hb)));
    hi = *(uint32_t*)&hp;
    lo = *(uint32_t*)&lp;
}
__device__ __forceinline__ float get_rinv(const float* pmax, int r) {
    if (pmax == nullptr) return 1.0f;
    float m = 0.0f;
    #pragma unroll
    for (int j = 0; j < 8; j++) m = fmaxf(m, pmax[j * MM + r]);
    return 1.0f / (m + EPSV);
}

// ---------------------------------------------------------------------------
// fp16 split GEMM: D = (Ah [+ Al]) @ B^T (+bias).  BM=128, BN=128.
// ATERMS=2: A exact as fp16 hi+lo;  ATERMS=1: A rounded to fp16.
// B rounded to fp16 (residual ~2^-12, dropped).
// EPI 0: attn (gc<1024 -> zh/zl split, else v fp32)
// EPI 1: fp32 out + bias (freq-U, proj)
// EPI 2: split zh/zl + per-block row-max partials (out step)
// ---------------------------------------------------------------------------
template<int EPI, int ATERMS, int KB, int ALD, int NOUT>
__global__ __launch_bounds__(256, 2)
void mma_gemm(const __half* __restrict__ Ah, const __half* __restrict__ Al,
              const __half* __restrict__ B,
              const float* __restrict__ bias,
              float* __restrict__ outf,
              __half* __restrict__ outh, __half* __restrict__ outl,
              float* __restrict__ pmax)
{
    constexpr int BN     = 128;
    constexpr int BK     = 32;
    constexpr int STAGES = 3;
    constexpr int KT     = KB / BK;
    constexpr int LDS    = BK + 8;                 // halves, +16B pad
    constexpr int ROWB   = LDS * 2;                // 80 B/row
    constexpr int AROWS  = (ATERMS == 2) ? 256 : 128;
    constexpr int OFF_AL = 128 * ROWB;
    constexpr int OFF_B  = AROWS * ROWB;
    constexpr int STG    = (AROWS + BN) * ROWB;    // bytes / stage
    constexpr int NI     = 4;                      // (BN/4)/8

    extern __shared__ __align__(128) char smem[];
    const uint32_t sA = smem_u32(smem);

    const int tid  = threadIdx.x;
    const int wid  = tid >> 5, lane = tid & 31;
    const int wm   = wid >> 2, wn = wid & 3;
    const int row0 = blockIdx.y * 128;
    const int n0   = blockIdx.x * BN;

    float acc[4][NI][4];
    #pragma unroll
    for (int mi = 0; mi < 4; mi++)
        #pragma unroll
        for (int ni = 0; ni < NI; ni++)
            #pragma unroll
            for (int r = 0; r < 4; r++) acc[mi][ni][r] = 0.0f;

    auto load_tiles = [&](int kt, int stage) {
        if (kt >= KT) return;
        const int chunk = tid & 3;
        const int kg    = kt * BK + chunk * 8;
        const uint32_t stg = sA + stage * STG;
        #pragma unroll
        for (int p = 0; p < 2; p++) {
            const int row = (tid >> 2) + p * 64;
            const size_t base = (size_t)(row0 + row) * ALD + kg;
            const uint32_t so = (uint32_t)(row * LDS + chunk * 8) * 2;
            cp16(stg + so, Ah + base);
            if (ATERMS == 2) cp16(stg + OFF_AL + so, Al + base);
        }
        #pragma unroll
        for (int p = 0; p < 2; p++) {
            const int row = (tid >> 2) + p * 64;
            const uint32_t so = (uint32_t)(row * LDS + chunk * 8) * 2;
            cp16(stg + OFF_B + so, B + ((size_t)(n0 + row) * KB + kg));
        }
    };

    #pragma unroll
    for (int s = 0; s < STAGES - 1; s++) { load_tiles(s, s); CP_COMMIT(); }

    for (int kt = 0; kt < KT; kt++) {
        CP_WAIT1();
        __syncthreads();
        load_tiles(kt + STAGES - 1, (kt + STAGES - 1) % STAGES);
        CP_COMMIT();

        const uint32_t stg = sA + (kt % STAGES) * STG;
        #pragma unroll
        for (int ks = 0; ks < 2; ks++) {
            const uint32_t aoff = (uint32_t)(ks * 16 + (lane >> 4) * 8) * 2;
            const uint32_t boff = (uint32_t)(ks * 16 + ((lane >> 3) & 1) * 8) * 2;
            uint32_t bfH[NI][2];
            #pragma unroll
            for (int ni = 0; ni < NI; ni++)
                ldmB(bfH[ni], stg + OFF_B +
                     (uint32_t)((wn * 32 + ni * 8 + (lane & 7)) * LDS) * 2 + boff);
            uint32_t afH[4][4];
            #pragma unroll
            for (int mi = 0; mi < 4; mi++)
                ldmA(afH[mi], stg +
                     (uint32_t)((wm * 64 + mi * 16 + (lane & 15)) * LDS) * 2 + aoff);
            #pragma unroll
            for (int mi = 0; mi < 4; mi++)
                #pragma unroll
                for (int ni = 0; ni < NI; ni++)
                    mma16816(acc[mi][ni], afH[mi], bfH[ni]);
            if (ATERMS == 2) {
                uint32_t afL[4][4];
                #pragma unroll
                for (int mi = 0; mi < 4; mi++)
                    ldmA(afL[mi], stg + OFF_AL +
                         (uint32_t)((wm * 64 + mi * 16 + (lane & 15)) * LDS) * 2 + aoff);
                #pragma unroll
                for (int mi = 0; mi < 4; mi++)
                    #pragma unroll
                    for (int ni = 0; ni < NI; ni++)
                        mma16816(acc[mi][ni], afL[mi], bfH[ni]);
            }
        }
    }
    CP_WAIT0();
    __syncthreads();

    // ---- epilogue ----
    float* pm = (float*)smem;
    float rmax[4][2];
    #pragma unroll
    for (int mi = 0; mi < 4; mi++) { rmax[mi][0] = 0.0f; rmax[mi][1] = 0.0f; }

    #pragma unroll
    for (int mi = 0; mi < 4; mi++) {
        const int R0 = row0 + wm * 64 + mi * 16 + (lane >> 2);
        const int R1 = R0 + 8;
        #pragma unroll
        for (int ni = 0; ni < NI; ni++) {
            const int gc = n0 + wn * 32 + ni * 8 + 2 * (lane & 3);
            const float b0 = bias[gc], b1 = bias[gc + 1];
            float v0 = acc[mi][ni][0] + b0, v1 = acc[mi][ni][1] + b1;
            float v2 = acc[mi][ni][2] + b0, v3 = acc[mi][ni][3] + b1;
            if (EPI == 0) {
                if (gc < Cc) {
                    uint32_t hi, lo;
                    splitH2(v0, v1, hi, lo);
                    *(uint32_t*)&outh[(size_t)R0 * Cc + gc] = hi;
                    *(uint32_t*)&outl[(size_t)R0 * Cc + gc] = lo;
                    splitH2(v2, v3, hi, lo);
                    *(uint32_t*)&outh[(size_t)R1 * Cc + gc] = hi;
                    *(uint32_t*)&outl[(size_t)R1 * Cc + gc] = lo;
                } else {
                    *(float2*)&outf[(size_t)R0 * Cc + gc - Cc] = make_float2(v0, v1);
                    *(float2*)&outf[(size_t)R1 * Cc + gc - Cc] = make_float2(v2, v3);
                }
            } else if (EPI == 1) {
                *(float2*)&outf[(size_t)R0 * NOUT + gc] = make_float2(v0, v1);
                *(float2*)&outf[(size_t)R1 * NOUT + gc] = make_float2(v2, v3);
            } else {
                uint32_t hi, lo;
                splitH2(v0, v1, hi, lo);
                *(uint32_t*)&outh[(size_t)R0 * NOUT + gc] = hi;
                *(uint32_t*)&outl[(size_t)R0 * NOUT + gc] = lo;
                splitH2(v2, v3, hi, lo);
                *(uint32_t*)&outh[(size_t)R1 * NOUT + gc] = hi;
                *(uint32_t*)&outl[(size_t)R1 * NOUT + gc] = lo;
                rmax[mi][0] = fmaxf(rmax[mi][0], fmaxf(fabsf(v0), fabsf(v1)));
                rmax[mi][1] = fmaxf(rmax[mi][1], fmaxf(fabsf(v2), fabsf(v3)));
            }
        }
    }

    if (EPI == 2) {
        #pragma unroll
        for (int mi = 0; mi < 4; mi++) {
            float m0 = rmax[mi][0], m1 = rmax[mi][1];
            #pragma unroll
            for (int off = 1; off < 4; off <<= 1) {
                m0 = fmaxf(m0, __shfl_xor_sync(0xffffffff, m0, off));
                m1 = fmaxf(m1, __shfl_xor_sync(0xffffffff, m1, off));
            }
            if ((lane & 3) == 0) {
                int lr = wm * 64 + mi * 16 + (lane >> 2);
                pm[lr * 4 + wn]       = m0;
                pm[(lr + 8) * 4 + wn] = m1;
            }
        }
        __syncthreads();
        if (tid < 128) {
            float m = fmaxf(fmaxf(pm[tid * 4], pm[tid * 4 + 1]),
                            fmaxf(pm[tid * 4 + 2], pm[tid * 4 + 3]));
            pmax[(size_t)blockIdx.x * MM + row0 + tid] = m;
        }
    }
}

// ---------------------------------------------------------------------------
// combine: f = rinv[t-n]*U1[t-n] (or c1) + rinv[t]*U2[t] + freq_b
//          sc = [sin f, cos f] split to fp16 hi/lo
// ---------------------------------------------------------------------------
__global__ __launch_bounds__(256)
void combine_k(const float* __restrict__ U, const float* __restrict__ pmax,
               const float* __restrict__ c1, const float* __restrict__ freq_b,
               __half* __restrict__ sch, __half* __restrict__ scl, int nShift)
{
    const int n   = threadIdx.x & 63;
    const int row = blockIdx.x * 4 + (threadIdx.x >> 6);
    const int t   = row & (Tt - 1);

    float u2 = U[(size_t)row * 128 + 64 + n] * get_rinv(pmax, row);
    float u1;
    if (t >= nShift) {
        int rp = row - nShift;
        u1 = U[(size_t)rp * 128 + n] * get_rinv(pmax, rp);
    } else {
        u1 = c1[n];
    }
    float f = u1 + u2 + freq_b[n];
    float s, c;
    sincosf(f, &s, &c);
    __half sh = __float2half_rn(s), ch = __float2half_rn(c);
    sch[(size_t)row * 128 + n]      = sh;
    scl[(size_t)row * 128 + n]      = __float2half_rn(s - __half2float(sh));
    sch[(size_t)row * 128 + 64 + n] = ch;
    scl[(size_t)row * 128 + 64 + n] = __float2half_rn(c - __half2float(ch));
}

// ---------------------------------------------------------------------------
// Prep kernels
// ---------------------------------------------------------------------------
__global__ void cvt_k(const float* __restrict__ s, __half* __restrict__ h, int n)
{
    for (int i = blockIdx.x * blockDim.x + threadIdx.x; i < n;
         i += gridDim.x * blockDim.x)
        h[i] = __float2half_rn(s[i]);
}
__global__ void tsplit_h(const float* __restrict__ W, __half* __restrict__ Th,
                         int K, int N)
{
    for (int i = blockIdx.x * blockDim.x + threadIdx.x; i < K * N;
         i += gridDim.x * blockDim.x) {
        int k = i / N, n = i - k * N;
        Th[(size_t)n * K + k] = __float2half_rn(W[i]);
    }
}
__global__ void fwt_k(const float* __restrict__ freq_W, __half* __restrict__ fW)
{
    for (int i = blockIdx.x * blockDim.x + threadIdx.x; i < 128 * 1024;
         i += gridDim.x * blockDim.x) {
        int n = i >> 10, k = i & 1023;
        float w = (n < 64) ? freq_W[(size_t)k * 64 + n]
                           : freq_W[(size_t)(1024 + k) * 64 + (n - 64)];
        fW[i] = __float2half_rn(w);
    }
}
__global__ void c1_k(const float* __restrict__ freq_W,
                     const float* __restrict__ identity, float* __restrict__ c1)
{
    __shared__ float red[256];
    const int n = blockIdx.x;
    float s = 0.0f;
    for (int k = threadIdx.x; k < 1024; k += 256)
        s += identity[k] * freq_W[(size_t)k * 64 + n];
    red[threadIdx.x] = s;
    __syncthreads();
    for (int o = 128; o > 0; o >>= 1) {
        if (threadIdx.x < o) red[threadIdx.x] += red[threadIdx.x + o];
        __syncthreads();
    }
    if (threadIdx.x == 0) c1[n] = red[0];
}
// p = (zh+zl)*rinv*v rounded to fp16 (1-term proj A)
__global__ __launch_bounds__(256)
void mulround_k(const __half* __restrict__ zh, const __half* __restrict__ zl,
                const float* __restrict__ pmax, const float* __restrict__ v,
                __half* __restrict__ ph)
{
    int wid = threadIdx.x >> 5, lane = threadIdx.x & 31;
    int r = blockIdx.x * 8 + wid;
    float rinv = get_rinv(pmax, r);
    #pragma unroll
    for (int j = 0; j < 8; j++) {
        int c = j * 128 + lane * 4;
        size_t b = (size_t)r * Cc + c;
        uint2 hw = *(const uint2*)&zh[b];
        uint2 lw = *(const uint2*)&zl[b];
        float4 vv = *(const float4*)&v[b];
        __half2 h0 = *(__half2*)&hw.x, h1 = *(__half2*)&hw.y;
        __half2 l0 = *(__half2*)&lw.x, l1 = *(__half2*)&lw.y;
        float2 f0 = __half22float2(h0), f1 = __half22float2(h1);
        float2 g0 = __half22float2(l0), g1 = __half22float2(l1);
        __half2 p0 = __halves2half2(
            __float2half_rn((f0.x + g0.x) * rinv * vv.x),
            __float2half_rn((f0.y + g0.y) * rinv * vv.y));
        __half2 p1 = __halves2half2(
            __float2half_rn((f1.x + g1.x) * rinv * vv.z),
            __float2half_rn((f1.y + g1.y) * rinv * vv.w));
        *(uint2*)&ph[b] = make_uint2(*(uint32_t*)&p0, *(uint32_t*)&p1);
    }
}

// ---------------------------------------------------------------------------
extern "C" void kernel_launch(void* const* d_in, const int* in_sizes, int n_in,
                              void* d_out, int out_size)
{
    (void)in_sizes; (void)n_in; (void)out_size;
    const float* x        = (const float*)d_in[0];
    const float* attn_W   = (const float*)d_in[1];
    const float* attn_b   = (const float*)d_in[2];
    const float* freq_W   = (const float*)d_in[3];
    const float* freq_b   = (const float*)d_in[4];
    const float* out_W    = (const float*)d_in[5];
    const float* out_b    = (const float*)d_in[6];
    const float* proj_W   = (const float*)d_in[7];
    const float* proj_b   = (const float*)d_in[8];
    const float* identity = (const float*)d_in[9];

    __half *xh, *zh, *zl, *sch, *scl, *aW, *fW, *oW, *pW;
    float *v, *u, *pmax, *c1, *zerob;
    cudaGetSymbolAddress((void**)&xh,  g_xh);
    cudaGetSymbolAddress((void**)&zh,  g_zh);  cudaGetSymbolAddress((void**)&zl,  g_zl);
    cudaGetSymbolAddress((void**)&v,   g_v);   cudaGetSymbolAddress((void**)&u,   g_u);
    cudaGetSymbolAddress((void**)&sch, g_sch); cudaGetSymbolAddress((void**)&scl, g_scl);
    cudaGetSymbolAddress((void**)&pmax,g_pmax);cudaGetSymbolAddress((void**)&c1,  g_c1);
    cudaGetSymbolAddress((void**)&zerob, g_zero);
    cudaGetSymbolAddress((void**)&aW,  g_aW);  cudaGetSymbolAddress((void**)&fW,  g_fW);
    cudaGetSymbolAddress((void**)&oW,  g_oW);  cudaGetSymbolAddress((void**)&pW,  g_pW);

    const int SMB2 = 3 * (256 + 128) * 80;   // 92160 (2-term)
    const int SMB1 = 3 * (128 + 128) * 80;   // 61440 (1-term)
    cudaFuncSetAttribute(mma_gemm<0, 1, 1024, 1024, 2048>,
                         cudaFuncAttributeMaxDynamicSharedMemorySize, SMB1);
    cudaFuncSetAttribute(mma_gemm<1, 2, 1024, 1024, 128>,
                         cudaFuncAttributeMaxDynamicSharedMemorySize, SMB2);
    cudaFuncSetAttribute(mma_gemm<2, 2, 128, 128, 1024>,
                         cudaFuncAttributeMaxDynamicSharedMemorySize, SMB2);
    cudaFuncSetAttribute(mma_gemm<1, 1, 1024, 1024, 1024>,
                         cudaFuncAttributeMaxDynamicSharedMemorySize, SMB1);

    // prep
    cvt_k<<<8192, 256>>>(x, xh, MM * Cc);
    tsplit_h<<<2048, 256>>>(attn_W, aW, 1024, 2048);
    fwt_k<<<256, 256>>>(freq_W, fW);
    tsplit_h<<<256, 256>>>(out_W, oW, 128, 1024);
    tsplit_h<<<1024, 256>>>(proj_W, pW, 1024, 1024);
    c1_k<<<64, 256>>>(freq_W, identity, c1);

    // attn: qv = x @ attn_W + attn_b -> q (zh/zl fp16 split) | v (fp32)
    mma_gemm<0, 1, 1024, 1024, 2048><<<dim3(16, 128), 256, SMB1>>>(
        xh, nullptr, aW, attn_b, v, zh, zl, nullptr);

    // log-scan
    int iter = 0;
    for (int n = 1; n < Tt; n <<= 1, iter++) {
        mma_gemm<1, 2, 1024, 1024, 128><<<dim3(1, 128), 256, SMB2>>>(
            zh, zl, fW, zerob, u, nullptr, nullptr, nullptr);
        combine_k<<<MM / 4, 256>>>(u, (iter == 0) ? nullptr : pmax,
                                   c1, freq_b, sch, scl, n);
        mma_gemm<2, 2, 128, 128, 1024><<<dim3(8, 128), 256, SMB2>>>(
            sch, scl, oW, out_b, nullptr, zh, zl, pmax);
    }

    // proj: out = (mmnorm(z) * v) @ proj_W + proj_b
    mulround_k<<<MM / 8, 256>>>(zh, zl, pmax, v, xh);
    mma_gemm<1, 1, 1024, 1024, 1024><<<dim3(8, 128), 256, SMB1>>>(
        xh, nullptr, pW, proj_b, (float*)d_out, nullptr, nullptr, nullptr);
}

// round 9
// speedup vs baseline: 9.5303x; 1.0092x over previous
#include <cuda_runtime.h>
#include <cuda_fp16.h>
#include <math.h>
#include <stdint.h>

#define MM   16384
#define Cc   1024
#define Tt   2048
#define EPSV 1e-6f

// ---------------------------------------------------------------------------
// Scratch (__device__ globals; no allocation allowed)
// ---------------------------------------------------------------------------
__device__ __half g_xh[MM * Cc];                  // x fp16; reused for q*v
__device__ __half g_zh[MM * Cc], g_zl[MM * Cc];   // scan state (unnormalized z)
__device__ float  g_v [MM * Cc];
__device__ float  g_u [2 * MM * 128];             // split-K partial U buffers
__device__ __half g_sch[MM * 128], g_scl[MM * 128];
__device__ float  g_pmax[8 * MM];
__device__ float  g_c1[64];
__device__ float  g_zero[2048];                   // zero bias (static init 0)
__device__ __half g_aW[2048 * 1024];              // attn_W^T  [N][K]
__device__ __half g_fW[128 * 1024];               // [W1|W2]^T [N][K]
__device__ __half g_oW[1024 * 128];               // out_W^T   [N][K]
__device__ __half g_pW[1024 * 1024];              // proj_W^T  [N][K]

// ---------------------------------------------------------------------------
__device__ __forceinline__ uint32_t smem_u32(const void* p) {
    uint32_t a;
    asm("{ .reg .u64 t; cvta.to.shared.u64 t, %1; cvt.u32.u64 %0, t; }"
        : "=r"(a) : "l"(p));
    return a;
}
__device__ __forceinline__ void cp16(uint32_t dst, const void* src) {
    asm volatile("cp.async.cg.shared.global [%0], [%1], 16;"
                 :: "r"(dst), "l"(src));
}
#define CP_COMMIT() asm volatile("cp.async.commit_group;")
#define CP_WAIT1()  asm volatile("cp.async.wait_group 1;")
#define CP_WAIT0()  asm volatile("cp.async.wait_group 0;")

__device__ __forceinline__ void ldmA(uint32_t* a, uint32_t addr) {
    asm volatile("ldmatrix.sync.aligned.m8n8.x4.shared.b16 {%0,%1,%2,%3}, [%4];"
                 : "=r"(a[0]), "=r"(a[1]), "=r"(a[2]), "=r"(a[3]) : "r"(addr));
}
__device__ __forceinline__ void ldmB(uint32_t* b, uint32_t addr) {
    asm volatile("ldmatrix.sync.aligned.m8n8.x2.shared.b16 {%0,%1}, [%2];"
                 : "=r"(b[0]), "=r"(b[1]) : "r"(addr));
}
__device__ __forceinline__ void mma16816(float* c, const uint32_t* a,
                                         const uint32_t* b) {
    asm volatile("mma.sync.aligned.m16n8k16.row.col.f32.f16.f16.f32 "
                 "{%0,%1,%2,%3}, {%4,%5,%6,%7}, {%8,%9}, {%0,%1,%2,%3};"
                 : "+f"(c[0]), "+f"(c[1]), "+f"(c[2]), "+f"(c[3])
                 : "r"(a[0]), "r"(a[1]), "r"(a[2]), "r"(a[3]),
                   "r"(b[0]), "r"(b[1]));
}
__device__ __forceinline__ void splitH2(float a, float b, uint32_t& hi, uint32_t& lo) {
    __half ha = __float2half_rn(a), hb = __float2half_rn(b);
    __half2 hp = __halves2half2(ha, hb);
    __half2 lp = __halves2half2(__float2half_rn(a - __half2float(ha)),
                                __float2half_rn(b - __half2float(hb)));
    hi = *(uint32_t*)&hp;
    lo = *(uint32_t*)&lp;
}
__device__ __forceinline__ float get_rinv(const float* pmax, int r) {
    if (pmax == nullptr) return 1.0f;
    float m = 0.0f;
    #pragma unroll
    for (int j = 0; j < 8; j++) m = fmaxf(m, pmax[j * MM + r]);
    return 1.0f / (m + EPSV);
}

// ---------------------------------------------------------------------------
// fp16 split GEMM: D = (Ah [+ Al]) @ B^T (+bias).  BM=128, BN=128.
// ATERMS=2: A exact as fp16 hi+lo;  ATERMS=1: A rounded to fp16.
// Split-K via blockIdx.z: each z-slice covers K columns [z*KB, (z+1)*KB) and
// writes its partial result to outf + z*MM*NOUT (EPI 1).  KLD = B row stride.
// EPI 0: attn (gc<1024 -> zh/zl split, else v fp32)
// EPI 1: fp32 out + bias (freq-U partials, proj)
// EPI 2: split zh/zl + per-block row-max partials (out step)
// ---------------------------------------------------------------------------
template<int EPI, int ATERMS, int KB, int KLD, int ALD, int NOUT>
__global__ __launch_bounds__(256, 2)
void mma_gemm(const __half* __restrict__ Ah, const __half* __restrict__ Al,
              const __half* __restrict__ B,
              const float* __restrict__ bias,
              float* __restrict__ outf,
              __half* __restrict__ outh, __half* __restrict__ outl,
              float* __restrict__ pmax)
{
    constexpr int BN     = 128;
    constexpr int BK     = 32;
    constexpr int STAGES = 3;
    constexpr int KT     = KB / BK;
    constexpr int LDS    = BK + 8;                 // halves, +16B pad
    constexpr int ROWB   = LDS * 2;                // 80 B/row
    constexpr int AROWS  = (ATERMS == 2) ? 256 : 128;
    constexpr int OFF_AL = 128 * ROWB;
    constexpr int OFF_B  = AROWS * ROWB;
    constexpr int STG    = (AROWS + BN) * ROWB;    // bytes / stage
    constexpr int NI     = 4;                      // (BN/4)/8

    extern __shared__ __align__(128) char smem[];
    const uint32_t sA = smem_u32(smem);

    const int tid  = threadIdx.x;
    const int wid  = tid >> 5, lane = tid & 31;
    const int wm   = wid >> 2, wn = wid & 3;
    const int row0 = blockIdx.y * 128;
    const int n0   = blockIdx.x * BN;
    const int kz   = blockIdx.z * KB;              // split-K column offset

    float acc[4][NI][4];
    #pragma unroll
    for (int mi = 0; mi < 4; mi++)
        #pragma unroll
        for (int ni = 0; ni < NI; ni++)
            #pragma unroll
            for (int r = 0; r < 4; r++) acc[mi][ni][r] = 0.0f;

    auto load_tiles = [&](int kt, int stage) {
        if (kt >= KT) return;
        const int chunk = tid & 3;
        const int kg    = kz + kt * BK + chunk * 8;
        const uint32_t stg = sA + stage * STG;
        #pragma unroll
        for (int p = 0; p < 2; p++) {
            const int row = (tid >> 2) + p * 64;
            const size_t base = (size_t)(row0 + row) * ALD + kg;
            const uint32_t so = (uint32_t)(row * LDS + chunk * 8) * 2;
            cp16(stg + so, Ah + base);
            if (ATERMS == 2) cp16(stg + OFF_AL + so, Al + base);
        }
        #pragma unroll
        for (int p = 0; p < 2; p++) {
            const int row = (tid >> 2) + p * 64;
            const uint32_t so = (uint32_t)(row * LDS + chunk * 8) * 2;
            cp16(stg + OFF_B + so, B + ((size_t)(n0 + row) * KLD + kg));
        }
    };

    #pragma unroll
    for (int s = 0; s < STAGES - 1; s++) { load_tiles(s, s); CP_COMMIT(); }

    for (int kt = 0; kt < KT; kt++) {
        CP_WAIT1();
        __syncthreads();
        load_tiles(kt + STAGES - 1, (kt + STAGES - 1) % STAGES);
        CP_COMMIT();

        const uint32_t stg = sA + (kt % STAGES) * STG;
        #pragma unroll
        for (int ks = 0; ks < 2; ks++) {
            const uint32_t aoff = (uint32_t)(ks * 16 + (lane >> 4) * 8) * 2;
            const uint32_t boff = (uint32_t)(ks * 16 + ((lane >> 3) & 1) * 8) * 2;
            uint32_t bfH[NI][2];
            #pragma unroll
            for (int ni = 0; ni < NI; ni++)
                ldmB(bfH[ni], stg + OFF_B +
                     (uint32_t)((wn * 32 + ni * 8 + (lane & 7)) * LDS) * 2 + boff);
            uint32_t afH[4][4];
            #pragma unroll
            for (int mi = 0; mi < 4; mi++)
                ldmA(afH[mi], stg +
                     (uint32_t)((wm * 64 + mi * 16 + (lane & 15)) * LDS) * 2 + aoff);
            #pragma unroll
            for (int mi = 0; mi < 4; mi++)
                #pragma unroll
                for (int ni = 0; ni < NI; ni++)
                    mma16816(acc[mi][ni], afH[mi], bfH[ni]);
            if (ATERMS == 2) {
                uint32_t afL[4][4];
                #pragma unroll
                for (int mi = 0; mi < 4; mi++)
                    ldmA(afL[mi], stg + OFF_AL +
                         (uint32_t)((wm * 64 + mi * 16 + (lane & 15)) * LDS) * 2 + aoff);
                #pragma unroll
                for (int mi = 0; mi < 4; mi++)
                    #pragma unroll
                    for (int ni = 0; ni < NI; ni++)
                        mma16816(acc[mi][ni], afL[mi], bfH[ni]);
            }
        }
    }
    CP_WAIT0();
    __syncthreads();

    // ---- epilogue ----
    float* pm = (float*)smem;
    float* outz = outf + (size_t)blockIdx.z * MM * NOUT;   // split-K partial
    float rmax[4][2];
    #pragma unroll
    for (int mi = 0; mi < 4; mi++) { rmax[mi][0] = 0.0f; rmax[mi][1] = 0.0f; }

    #pragma unroll
    for (int mi = 0; mi < 4; mi++) {
        const int R0 = row0 + wm * 64 + mi * 16 + (lane >> 2);
        const int R1 = R0 + 8;
        #pragma unroll
        for (int ni = 0; ni < NI; ni++) {
            const int gc = n0 + wn * 32 + ni * 8 + 2 * (lane & 3);
            const float b0 = bias[gc], b1 = bias[gc + 1];
            float v0 = acc[mi][ni][0] + b0, v1 = acc[mi][ni][1] + b1;
            float v2 = acc[mi][ni][2] + b0, v3 = acc[mi][ni][3] + b1;
            if (EPI == 0) {
                if (gc < Cc) {
                    uint32_t hi, lo;
                    splitH2(v0, v1, hi, lo);
                    *(uint32_t*)&outh[(size_t)R0 * Cc + gc] = hi;
                    *(uint32_t*)&outl[(size_t)R0 * Cc + gc] = lo;
                    splitH2(v2, v3, hi, lo);
                    *(uint32_t*)&outh[(size_t)R1 * Cc + gc] = hi;
                    *(uint32_t*)&outl[(size_t)R1 * Cc + gc] = lo;
                } else {
                    *(float2*)&outf[(size_t)R0 * Cc + gc - Cc] = make_float2(v0, v1);
                    *(float2*)&outf[(size_t)R1 * Cc + gc - Cc] = make_float2(v2, v3);
                }
            } else if (EPI == 1) {
                *(float2*)&outz[(size_t)R0 * NOUT + gc] = make_float2(v0, v1);
                *(float2*)&outz[(size_t)R1 * NOUT + gc] = make_float2(v2, v3);
            } else {
                uint32_t hi, lo;
                splitH2(v0, v1, hi, lo);
                *(uint32_t*)&outh[(size_t)R0 * NOUT + gc] = hi;
                *(uint32_t*)&outl[(size_t)R0 * NOUT + gc] = lo;
                splitH2(v2, v3, hi, lo);
                *(uint32_t*)&outh[(size_t)R1 * NOUT + gc] = hi;
                *(uint32_t*)&outl[(size_t)R1 * NOUT + gc] = lo;
                rmax[mi][0] = fmaxf(rmax[mi][0], fmaxf(fabsf(v0), fabsf(v1)));
                rmax[mi][1] = fmaxf(rmax[mi][1], fmaxf(fabsf(v2), fabsf(v3)));
            }
        }
    }

    if (EPI == 2) {
        #pragma unroll
        for (int mi = 0; mi < 4; mi++) {
            float m0 = rmax[mi][0], m1 = rmax[mi][1];
            #pragma unroll
            for (int off = 1; off < 4; off <<= 1) {
                m0 = fmaxf(m0, __shfl_xor_sync(0xffffffff, m0, off));
                m1 = fmaxf(m1, __shfl_xor_sync(0xffffffff, m1, off));
            }
            if ((lane & 3) == 0) {
                int lr = wm * 64 + mi * 16 + (lane >> 2);
                pm[lr * 4 + wn]       = m0;
                pm[(lr + 8) * 4 + wn] = m1;
            }
        }
        __syncthreads();
        if (tid < 128) {
            float m = fmaxf(fmaxf(pm[tid * 4], pm[tid * 4 + 1]),
                            fmaxf(pm[tid * 4 + 2], pm[tid * 4 + 3]));
            pmax[(size_t)blockIdx.x * MM + row0 + tid] = m;
        }
    }
}

// ---------------------------------------------------------------------------
// combine: sums split-K partial U buffers, applies rinv row scales + shift,
// then sc = [sin f, cos f] split to fp16 hi/lo.
// ---------------------------------------------------------------------------
__global__ __launch_bounds__(256)
void combine_k(const float* __restrict__ U, const float* __restrict__ pmax,
               const float* __restrict__ c1, const float* __restrict__ freq_b,
               __half* __restrict__ sch, __half* __restrict__ scl, int nShift)
{
    const int n   = threadIdx.x & 63;
    const int row = blockIdx.x * 4 + (threadIdx.x >> 6);
    const int t   = row & (Tt - 1);
    const float* U2 = U + (size_t)MM * 128;

    size_t i2 = (size_t)row * 128 + 64 + n;
    float u2 = (U[i2] + U2[i2]) * get_rinv(pmax, row);
    float u1;
    if (t >= nShift) {
        int rp = row - nShift;
        size_t i1 = (size_t)rp * 128 + n;
        u1 = (U[i1] + U2[i1]) * get_rinv(pmax, rp);
    } else {
        u1 = c1[n];
    }
    float f = u1 + u2 + freq_b[n];
    float s, c;
    sincosf(f, &s, &c);
    __half sh = __float2half_rn(s), ch = __float2half_rn(c);
    sch[(size_t)row * 128 + n]      = sh;
    scl[(size_t)row * 128 + n]      = __float2half_rn(s - __half2float(sh));
    sch[(size_t)row * 128 + 64 + n] = ch;
    scl[(size_t)row * 128 + 64 + n] = __float2half_rn(c - __half2float(ch));
}

// ---------------------------------------------------------------------------
// Prep kernels
// ---------------------------------------------------------------------------
__global__ void cvt_k(const float* __restrict__ s, __half* __restrict__ h, int n)
{
    for (int i = blockIdx.x * blockDim.x + threadIdx.x; i < n;
         i += gridDim.x * blockDim.x)
        h[i] = __float2half_rn(s[i]);
}
__global__ void tsplit_h(const float* __restrict__ W, __half* __restrict__ Th,
                         int K, int N)
{
    for (int i = blockIdx.x * blockDim.x + threadIdx.x; i < K * N;
         i += gridDim.x * blockDim.x) {
        int k = i / N, n = i - k * N;
        Th[(size_t)n * K + k] = __float2half_rn(W[i]);
    }
}
__global__ void fwt_k(const float* __restrict__ freq_W, __half* __restrict__ fW)
{
    for (int i = blockIdx.x * blockDim.x + threadIdx.x; i < 128 * 1024;
         i += gridDim.x * blockDim.x) {
        int n = i >> 10, k = i & 1023;
        float w = (n < 64) ? freq_W[(size_t)k * 64 + n]
                           : freq_W[(size_t)(1024 + k) * 64 + (n - 64)];
        fW[i] = __float2half_rn(w);
    }
}
__global__ void c1_k(const float* __restrict__ freq_W,
                     const float* __restrict__ identity, float* __restrict__ c1)
{
    __shared__ float red[256];
    const int n = blockIdx.x;
    float s = 0.0f;
    for (int k = threadIdx.x; k < 1024; k += 256)
        s += identity[k] * freq_W[(size_t)k * 64 + n];
    red[threadIdx.x] = s;
    __syncthreads();
    for (int o = 128; o > 0; o >>= 1) {
        if (threadIdx.x < o) red[threadIdx.x] += red[threadIdx.x + o];
        __syncthreads();
    }
    if (threadIdx.x == 0) c1[n] = red[0];
}
// p = (zh+zl)*rinv*v rounded to fp16 (1-term proj A)
__global__ __launch_bounds__(256)
void mulround_k(const __half* __restrict__ zh, const __half* __restrict__ zl,
                const float* __restrict__ pmax, const float* __restrict__ v,
                __half* __restrict__ ph)
{
    int wid = threadIdx.x >> 5, lane = threadIdx.x & 31;
    int r = blockIdx.x * 8 + wid;
    float rinv = get_rinv(pmax, r);
    #pragma unroll
    for (int j = 0; j < 8; j++) {
        int c = j * 128 + lane * 4;
        size_t b = (size_t)r * Cc + c;
        uint2 hw = *(const uint2*)&zh[b];
        uint2 lw = *(const uint2*)&zl[b];
        float4 vv = *(const float4*)&v[b];
        __half2 h0 = *(__half2*)&hw.x, h1 = *(__half2*)&hw.y;
        __half2 l0 = *(__half2*)&lw.x, l1 = *(__half2*)&lw.y;
        float2 f0 = __half22float2(h0), f1 = __half22float2(h1);
        float2 g0 = __half22float2(l0), g1 = __half22float2(l1);
        __half2 p0 = __halves2half2(
            __float2half_rn((f0.x + g0.x) * rinv * vv.x),
            __float2half_rn((f0.y + g0.y) * rinv * vv.y));
        __half2 p1 = __halves2half2(
            __float2half_rn((f1.x + g1.x) * rinv * vv.z),
            __float2half_rn((f1.y + g1.y) * rinv * vv.w));
        *(uint2*)&ph[b] = make_uint2(*(uint32_t*)&p0, *(uint32_t*)&p1);
    }
}

// ---------------------------------------------------------------------------
extern "C" void kernel_launch(void* const* d_in, const int* in_sizes, int n_in,
                              void* d_out, int out_size)
{
    (void)in_sizes; (void)n_in; (void)out_size;
    const float* x        = (const float*)d_in[0];
    const float* attn_W   = (const float*)d_in[1];
    const float* attn_b   = (const float*)d_in[2];
    const float* freq_W   = (const float*)d_in[3];
    const float* freq_b   = (const float*)d_in[4];
    const float* out_W    = (const float*)d_in[5];
    const float* out_b    = (const float*)d_in[6];
    const float* proj_W   = (const float*)d_in[7];
    const float* proj_b   = (const float*)d_in[8];
    const float* identity = (const float*)d_in[9];

    __half *xh, *zh, *zl, *sch, *scl, *aW, *fW, *oW, *pW;
    float *v, *u, *pmax, *c1, *zerob;
    cudaGetSymbolAddress((void**)&xh,  g_xh);
    cudaGetSymbolAddress((void**)&zh,  g_zh);  cudaGetSymbolAddress((void**)&zl,  g_zl);
    cudaGetSymbolAddress((void**)&v,   g_v);   cudaGetSymbolAddress((void**)&u,   g_u);
    cudaGetSymbolAddress((void**)&sch, g_sch); cudaGetSymbolAddress((void**)&scl, g_scl);
    cudaGetSymbolAddress((void**)&pmax,g_pmax);cudaGetSymbolAddress((void**)&c1,  g_c1);
    cudaGetSymbolAddress((void**)&zerob, g_zero);
    cudaGetSymbolAddress((void**)&aW,  g_aW);  cudaGetSymbolAddress((void**)&fW,  g_fW);
    cudaGetSymbolAddress((void**)&oW,  g_oW);  cudaGetSymbolAddress((void**)&pW,  g_pW);

    const int SMB2 = 3 * (256 + 128) * 80;   // 92160 (2-term)
    const int SMB1 = 3 * (128 + 128) * 80;   // 61440 (1-term)
    cudaFuncSetAttribute(mma_gemm<0, 1, 1024, 1024, 1024, 2048>,
                         cudaFuncAttributeMaxDynamicSharedMemorySize, SMB1);
    cudaFuncSetAttribute(mma_gemm<1, 2, 512, 1024, 1024, 128>,
                         cudaFuncAttributeMaxDynamicSharedMemorySize, SMB2);
    cudaFuncSetAttribute(mma_gemm<2, 2, 128, 128, 128, 1024>,
                         cudaFuncAttributeMaxDynamicSharedMemorySize, SMB2);
    cudaFuncSetAttribute(mma_gemm<1, 1, 1024, 1024, 1024, 1024>,
                         cudaFuncAttributeMaxDynamicSharedMemorySize, SMB1);

    // prep
    cvt_k<<<8192, 256>>>(x, xh, MM * Cc);
    tsplit_h<<<2048, 256>>>(attn_W, aW, 1024, 2048);
    fwt_k<<<256, 256>>>(freq_W, fW);
    tsplit_h<<<256, 256>>>(out_W, oW, 128, 1024);
    tsplit_h<<<1024, 256>>>(proj_W, pW, 1024, 1024);
    c1_k<<<64, 256>>>(freq_W, identity, c1);

    // attn: qv = x @ attn_W + attn_b -> q (zh/zl fp16 split) | v (fp32)
    mma_gemm<0, 1, 1024, 1024, 1024, 2048><<<dim3(16, 128), 256, SMB1>>>(
        xh, nullptr, aW, attn_b, v, zh, zl, nullptr);

    // log-scan
    int iter = 0;
    for (int n = 1; n < Tt; n <<= 1, iter++) {
        // freq: U = z @ [W1|W2], split-K x2 (grid.z), 2 partial buffers
        mma_gemm<1, 2, 512, 1024, 1024, 128><<<dim3(1, 128, 2), 256, SMB2>>>(
            zh, zl, fW, zerob, u, nullptr, nullptr, nullptr);
        combine_k<<<MM / 4, 256>>>(u, (iter == 0) ? nullptr : pmax,
                                   c1, freq_b, sch, scl, n);
        mma_gemm<2, 2, 128, 128, 128, 1024><<<dim3(8, 128), 256, SMB2>>>(
            sch, scl, oW, out_b, nullptr, zh, zl, pmax);
    }

    // proj: out = (mmnorm(z) * v) @ proj_W + proj_b
    mulround_k<<<MM / 8, 256>>>(zh, zl, pmax, v, xh);
    mma_gemm<1, 1, 1024, 1024, 1024, 1024><<<dim3(8, 128), 256, SMB1>>>(
        xh, nullptr, pW, proj_b, (float*)d_out, nullptr, nullptr, nullptr);
}

// round 10
// speedup vs baseline: 12.6113x; 1.3233x over previous
#include <cuda_runtime.h>
#include <cuda_fp16.h>
#include <math.h>
#include <stdint.h>

#define MM   16384
#define Cc   1024
#define Tt   2048
#define EPSV 1e-6f

// ---------------------------------------------------------------------------
// Scratch (__device__ globals; no allocation allowed)
// ---------------------------------------------------------------------------
__device__ __half g_xh[MM * Cc];                  // x fp16; reused for q*v
__device__ __half g_zh[MM * Cc];                  // scan state (unnormalized z)
__device__ float  g_v [MM * Cc];
__device__ float  g_u [2 * MM * 128];             // split-K partial U buffers
__device__ __half g_sch[MM * 128];
__device__ float  g_pmax[8 * MM];
__device__ float  g_c1[64];
__device__ float  g_zero[2048];                   // zero bias (static init 0)
__device__ __half g_aW[2048 * 1024];              // attn_W^T  [N][K]
__device__ __half g_fW[128 * 1024];               // [W1|W2]^T [N][K]
__device__ __half g_oW[1024 * 128];               // out_W^T   [N][K]
__device__ __half g_pW[1024 * 1024];              // proj_W^T  [N][K]

// ---------------------------------------------------------------------------
__device__ __forceinline__ uint32_t smem_u32(const void* p) {
    uint32_t a;
    asm("{ .reg .u64 t; cvta.to.shared.u64 t, %1; cvt.u32.u64 %0, t; }"
        : "=r"(a) : "l"(p));
    return a;
}
__device__ __forceinline__ void cp16(uint32_t dst, const void* src) {
    asm volatile("cp.async.cg.shared.global [%0], [%1], 16;"
                 :: "r"(dst), "l"(src));
}
#define CP_COMMIT() asm volatile("cp.async.commit_group;")
#define CP_WAIT1()  asm volatile("cp.async.wait_group 1;")
#define CP_WAIT0()  asm volatile("cp.async.wait_group 0;")

__device__ __forceinline__ void ldmA(uint32_t* a, uint32_t addr) {
    asm volatile("ldmatrix.sync.aligned.m8n8.x4.shared.b16 {%0,%1,%2,%3}, [%4];"
                 : "=r"(a[0]), "=r"(a[1]), "=r"(a[2]), "=r"(a[3]) : "r"(addr));
}
__device__ __forceinline__ void ldmB(uint32_t* b, uint32_t addr) {
    asm volatile("ldmatrix.sync.aligned.m8n8.x2.shared.b16 {%0,%1}, [%2];"
                 : "=r"(b[0]), "=r"(b[1]) : "r"(addr));
}
__device__ __forceinline__ void mma16816(float* c, const uint32_t* a,
                                         const uint32_t* b) {
    asm volatile("mma.sync.aligned.m16n8k16.row.col.f32.f16.f16.f32 "
                 "{%0,%1,%2,%3}, {%4,%5,%6,%7}, {%8,%9}, {%0,%1,%2,%3};"
                 : "+f"(c[0]), "+f"(c[1]), "+f"(c[2]), "+f"(c[3])
                 : "r"(a[0]), "r"(a[1]), "r"(a[2]), "r"(a[3]),
                   "r"(b[0]), "r"(b[1]));
}
__device__ __forceinline__ uint32_t roundH2(float a, float b) {
    __half2 hp = __halves2half2(__float2half_rn(a), __float2half_rn(b));
    return *(uint32_t*)&hp;
}
__device__ __forceinline__ float get_rinv(const float* pmax, int r) {
    if (pmax == nullptr) return 1.0f;
    float m = 0.0f;
    #pragma unroll
    for (int j = 0; j < 8; j++) m = fmaxf(m, pmax[j * MM + r]);
    return 1.0f / (m + EPSV);
}

// ---------------------------------------------------------------------------
// fp16 GEMM: D = A @ B^T (+bias).  BM=128, BN=128, BK=32, 3-stage cp.async.
// A and B rounded to fp16.  Split-K via blockIdx.z (EPI 1 partials).
// EPI 0: attn (gc<1024 -> zh fp16, else v fp32)
// EPI 1: fp32 out + bias (freq-U partials, proj)
// EPI 2: fp16 zh + per-block row-max partials (out step)
// ---------------------------------------------------------------------------
template<int EPI, int KB, int KLD, int ALD, int NOUT>
__global__ __launch_bounds__(256, 2)
void mma_gemm(const __half* __restrict__ Ah,
              const __half* __restrict__ B,
              const float* __restrict__ bias,
              float* __restrict__ outf,
              __half* __restrict__ outh,
              float* __restrict__ pmax)
{
    constexpr int BN     = 128;
    constexpr int BK     = 32;
    constexpr int STAGES = 3;
    constexpr int KT     = KB / BK;
    constexpr int LDS    = BK + 8;                 // halves, +16B pad
    constexpr int ROWB   = LDS * 2;                // 80 B/row
    constexpr int OFF_B  = 128 * ROWB;
    constexpr int STG    = (128 + BN) * ROWB;      // 20480 B / stage
    constexpr int NI     = 4;

    extern __shared__ __align__(128) char smem[];
    const uint32_t sA = smem_u32(smem);

    const int tid  = threadIdx.x;
    const int wid  = tid >> 5, lane = tid & 31;
    const int wm   = wid >> 2, wn = wid & 3;
    const int row0 = blockIdx.y * 128;
    const int n0   = blockIdx.x * BN;
    const int kz   = blockIdx.z * KB;              // split-K column offset

    float acc[4][NI][4];
    #pragma unroll
    for (int mi = 0; mi < 4; mi++)
        #pragma unroll
        for (int ni = 0; ni < NI; ni++)
            #pragma unroll
            for (int r = 0; r < 4; r++) acc[mi][ni][r] = 0.0f;

    auto load_tiles = [&](int kt, int stage) {
        if (kt >= KT) return;
        const int chunk = tid & 3;
        const int kg    = kz + kt * BK + chunk * 8;
        const uint32_t stg = sA + stage * STG;
        #pragma unroll
        for (int p = 0; p < 2; p++) {
            const int row = (tid >> 2) + p * 64;
            const uint32_t so = (uint32_t)(row * LDS + chunk * 8) * 2;
            cp16(stg + so, Ah + (size_t)(row0 + row) * ALD + kg);
            cp16(stg + OFF_B + so, B + ((size_t)(n0 + row) * KLD + kg));
        }
    };

    #pragma unroll
    for (int s = 0; s < STAGES - 1; s++) { load_tiles(s, s); CP_COMMIT(); }

    for (int kt = 0; kt < KT; kt++) {
        CP_WAIT1();
        __syncthreads();
        load_tiles(kt + STAGES - 1, (kt + STAGES - 1) % STAGES);
        CP_COMMIT();

        const uint32_t stg = sA + (kt % STAGES) * STG;
        #pragma unroll
        for (int ks = 0; ks < 2; ks++) {
            const uint32_t aoff = (uint32_t)(ks * 16 + (lane >> 4) * 8) * 2;
            const uint32_t boff = (uint32_t)(ks * 16 + ((lane >> 3) & 1) * 8) * 2;
            uint32_t bfH[NI][2];
            #pragma unroll
            for (int ni = 0; ni < NI; ni++)
                ldmB(bfH[ni], stg + OFF_B +
                     (uint32_t)((wn * 32 + ni * 8 + (lane & 7)) * LDS) * 2 + boff);
            uint32_t afH[4][4];
            #pragma unroll
            for (int mi = 0; mi < 4; mi++)
                ldmA(afH[mi], stg +
                     (uint32_t)((wm * 64 + mi * 16 + (lane & 15)) * LDS) * 2 + aoff);
            #pragma unroll
            for (int mi = 0; mi < 4; mi++)
                #pragma unroll
                for (int ni = 0; ni < NI; ni++)
                    mma16816(acc[mi][ni], afH[mi], bfH[ni]);
        }
    }
    CP_WAIT0();
    __syncthreads();

    // ---- epilogue ----
    float* pm = (float*)smem;
    float* outz = outf + (size_t)blockIdx.z * MM * NOUT;   // split-K partial
    float rmax[4][2];
    #pragma unroll
    for (int mi = 0; mi < 4; mi++) { rmax[mi][0] = 0.0f; rmax[mi][1] = 0.0f; }

    #pragma unroll
    for (int mi = 0; mi < 4; mi++) {
        const int R0 = row0 + wm * 64 + mi * 16 + (lane >> 2);
        const int R1 = R0 + 8;
        #pragma unroll
        for (int ni = 0; ni < NI; ni++) {
            const int gc = n0 + wn * 32 + ni * 8 + 2 * (lane & 3);
            const float b0 = bias[gc], b1 = bias[gc + 1];
            float v0 = acc[mi][ni][0] + b0, v1 = acc[mi][ni][1] + b1;
            float v2 = acc[mi][ni][2] + b0, v3 = acc[mi][ni][3] + b1;
            if (EPI == 0) {
                if (gc < Cc) {
                    *(uint32_t*)&outh[(size_t)R0 * Cc + gc] = roundH2(v0, v1);
                    *(uint32_t*)&outh[(size_t)R1 * Cc + gc] = roundH2(v2, v3);
                } else {
                    *(float2*)&outf[(size_t)R0 * Cc + gc - Cc] = make_float2(v0, v1);
                    *(float2*)&outf[(size_t)R1 * Cc + gc - Cc] = make_float2(v2, v3);
                }
            } else if (EPI == 1) {
                *(float2*)&outz[(size_t)R0 * NOUT + gc] = make_float2(v0, v1);
                *(float2*)&outz[(size_t)R1 * NOUT + gc] = make_float2(v2, v3);
            } else {
                *(uint32_t*)&outh[(size_t)R0 * NOUT + gc] = roundH2(v0, v1);
                *(uint32_t*)&outh[(size_t)R1 * NOUT + gc] = roundH2(v2, v3);
                rmax[mi][0] = fmaxf(rmax[mi][0], fmaxf(fabsf(v0), fabsf(v1)));
                rmax[mi][1] = fmaxf(rmax[mi][1], fmaxf(fabsf(v2), fabsf(v3)));
            }
        }
    }

    if (EPI == 2) {
        #pragma unroll
        for (int mi = 0; mi < 4; mi++) {
            float m0 = rmax[mi][0], m1 = rmax[mi][1];
            #pragma unroll
            for (int off = 1; off < 4; off <<= 1) {
                m0 = fmaxf(m0, __shfl_xor_sync(0xffffffff, m0, off));
                m1 = fmaxf(m1, __shfl_xor_sync(0xffffffff, m1, off));
            }
            if ((lane & 3) == 0) {
                int lr = wm * 64 + mi * 16 + (lane >> 2);
                pm[lr * 4 + wn]       = m0;
                pm[(lr + 8) * 4 + wn] = m1;
            }
        }
        __syncthreads();
        if (tid < 128) {
            float m = fmaxf(fmaxf(pm[tid * 4], pm[tid * 4 + 1]),
                            fmaxf(pm[tid * 4 + 2], pm[tid * 4 + 3]));
            pmax[(size_t)blockIdx.x * MM + row0 + tid] = m;
        }
    }
}

// ---------------------------------------------------------------------------
// combine: sums split-K partial U buffers, applies rinv row scales + shift,
// then sc = [sin f, cos f] rounded to fp16.
// ---------------------------------------------------------------------------
__global__ __launch_bounds__(256)
void combine_k(const float* __restrict__ U, const float* __restrict__ pmax,
               const float* __restrict__ c1, const float* __restrict__ freq_b,
               __half* __restrict__ sch, int nShift)
{
    const int n   = threadIdx.x & 63;
    const int row = blockIdx.x * 4 + (threadIdx.x >> 6);
    const int t   = row & (Tt - 1);
    const float* U2 = U + (size_t)MM * 128;

    size_t i2 = (size_t)row * 128 + 64 + n;
    float u2 = (U[i2] + U2[i2]) * get_rinv(pmax, row);
    float u1;
    if (t >= nShift) {
        int rp = row - nShift;
        size_t i1 = (size_t)rp * 128 + n;
        u1 = (U[i1] + U2[i1]) * get_rinv(pmax, rp);
    } else {
        u1 = c1[n];
    }
    float f = u1 + u2 + freq_b[n];
    float s, c;
    sincosf(f, &s, &c);
    sch[(size_t)row * 128 + n]      = __float2half_rn(s);
    sch[(size_t)row * 128 + 64 + n] = __float2half_rn(c);
}

// ---------------------------------------------------------------------------
// Prep kernels
// ---------------------------------------------------------------------------
__global__ void cvt_k(const float* __restrict__ s, __half* __restrict__ h, int n)
{
    for (int i = blockIdx.x * blockDim.x + threadIdx.x; i < n;
         i += gridDim.x * blockDim.x)
        h[i] = __float2half_rn(s[i]);
}
__global__ void tsplit_h(const float* __restrict__ W, __half* __restrict__ Th,
                         int K, int N)
{
    for (int i = blockIdx.x * blockDim.x + threadIdx.x; i < K * N;
         i += gridDim.x * blockDim.x) {
        int k = i / N, n = i - k * N;
        Th[(size_t)n * K + k] = __float2half_rn(W[i]);
    }
}
__global__ void fwt_k(const float* __restrict__ freq_W, __half* __restrict__ fW)
{
    for (int i = blockIdx.x * blockDim.x + threadIdx.x; i < 128 * 1024;
         i += gridDim.x * blockDim.x) {
        int n = i >> 10, k = i & 1023;
        float w = (n < 64) ? freq_W[(size_t)k * 64 + n]
                           : freq_W[(size_t)(1024 + k) * 64 + (n - 64)];
        fW[i] = __float2half_rn(w);
    }
}
__global__ void c1_k(const float* __restrict__ freq_W,
                     const float* __restrict__ identity, float* __restrict__ c1)
{
    __shared__ float red[256];
    const int n = blockIdx.x;
    float s = 0.0f;
    for (int k = threadIdx.x; k < 1024; k += 256)
        s += identity[k] * freq_W[(size_t)k * 64 + n];
    red[threadIdx.x] = s;
    __syncthreads();
    for (int o = 128; o > 0; o >>= 1) {
        if (threadIdx.x < o) red[threadIdx.x] += red[threadIdx.x + o];
        __syncthreads();
    }
    if (threadIdx.x == 0) c1[n] = red[0];
}
// p = zh*rinv*v rounded to fp16 (proj A)
__global__ __launch_bounds__(256)
void mulround_k(const __half* __restrict__ zh, const float* __restrict__ pmax,
                const float* __restrict__ v, __half* __restrict__ ph)
{
    int wid = threadIdx.x >> 5, lane = threadIdx.x & 31;
    int r = blockIdx.x * 8 + wid;
    float rinv = get_rinv(pmax, r);
    #pragma unroll
    for (int j = 0; j < 8; j++) {
        int c = j * 128 + lane * 4;
        size_t b = (size_t)r * Cc + c;
        uint2 hw = *(const uint2*)&zh[b];
        float4 vv = *(const float4*)&v[b];
        float2 f0 = __half22float2(*(__half2*)&hw.x);
        float2 f1 = __half22float2(*(__half2*)&hw.y);
        uint2 o;
        o.x = roundH2(f0.x * rinv * vv.x, f0.y * rinv * vv.y);
        o.y = roundH2(f1.x * rinv * vv.z, f1.y * rinv * vv.w);
        *(uint2*)&ph[b] = o;
    }
}

// ---------------------------------------------------------------------------
extern "C" void kernel_launch(void* const* d_in, const int* in_sizes, int n_in,
                              void* d_out, int out_size)
{
    (void)in_sizes; (void)n_in; (void)out_size;
    const float* x        = (const float*)d_in[0];
    const float* attn_W   = (const float*)d_in[1];
    const float* attn_b   = (const float*)d_in[2];
    const float* freq_W   = (const float*)d_in[3];
    const float* freq_b   = (const float*)d_in[4];
    const float* out_W    = (const float*)d_in[5];
    const float* out_b    = (const float*)d_in[6];
    const float* proj_W   = (const float*)d_in[7];
    const float* proj_b   = (const float*)d_in[8];
    const float* identity = (const float*)d_in[9];

    __half *xh, *zh, *sch, *aW, *fW, *oW, *pW;
    float *v, *u, *pmax, *c1, *zerob;
    cudaGetSymbolAddress((void**)&xh,  g_xh);
    cudaGetSymbolAddress((void**)&zh,  g_zh);
    cudaGetSymbolAddress((void**)&v,   g_v);   cudaGetSymbolAddress((void**)&u,   g_u);
    cudaGetSymbolAddress((void**)&sch, g_sch);
    cudaGetSymbolAddress((void**)&pmax,g_pmax);cudaGetSymbolAddress((void**)&c1,  g_c1);
    cudaGetSymbolAddress((void**)&zerob, g_zero);
    cudaGetSymbolAddress((void**)&aW,  g_aW);  cudaGetSymbolAddress((void**)&fW,  g_fW);
    cudaGetSymbolAddress((void**)&oW,  g_oW);  cudaGetSymbolAddress((void**)&pW,  g_pW);

    const int SMB = 3 * (128 + 128) * 80;   // 61440
    cudaFuncSetAttribute(mma_gemm<0, 1024, 1024, 1024, 2048>,
                         cudaFuncAttributeMaxDynamicSharedMemorySize, SMB);
    cudaFuncSetAttribute(mma_gemm<1, 512, 1024, 1024, 128>,
                         cudaFuncAttributeMaxDynamicSharedMemorySize, SMB);
    cudaFuncSetAttribute(mma_gemm<2, 128, 128, 128, 1024>,
                         cudaFuncAttributeMaxDynamicSharedMemorySize, SMB);
    cudaFuncSetAttribute(mma_gemm<1, 1024, 1024, 1024, 1024>,
                         cudaFuncAttributeMaxDynamicSharedMemorySize, SMB);

    // prep
    cvt_k<<<8192, 256>>>(x, xh, MM * Cc);
    tsplit_h<<<2048, 256>>>(attn_W, aW, 1024, 2048);
    fwt_k<<<256, 256>>>(freq_W, fW);
    tsplit_h<<<256, 256>>>(out_W, oW, 128, 1024);
    tsplit_h<<<1024, 256>>>(proj_W, pW, 1024, 1024);
    c1_k<<<64, 256>>>(freq_W, identity, c1);

    // attn: qv = x @ attn_W + attn_b -> q (zh fp16) | v (fp32)
    mma_gemm<0, 1024, 1024, 1024, 2048><<<dim3(16, 128), 256, SMB>>>(
        xh, aW, attn_b, v, zh, nullptr);

    // log-scan
    int iter = 0;
    for (int n = 1; n < Tt; n <<= 1, iter++) {
        // freq: U = z @ [W1|W2], split-K x2 (grid.z), 2 partial buffers
        mma_gemm<1, 512, 1024, 1024, 128><<<dim3(1, 128, 2), 256, SMB>>>(
            zh, fW, zerob, u, nullptr, nullptr);
        combine_k<<<MM / 4, 256>>>(u, (iter == 0) ? nullptr : pmax,
                                   c1, freq_b, sch, n);
        mma_gemm<2, 128, 128, 128, 1024><<<dim3(8, 128), 256, SMB>>>(
            sch, oW, out_b, nullptr, zh, pmax);
    }

    // proj: out = (mmnorm(z) * v) @ proj_W + proj_b
    mulround_k<<<MM / 8, 256>>>(zh, pmax, v, xh);
    mma_gemm<1, 1024, 1024, 1024, 1024><<<dim3(8, 128), 256, SMB>>>(
        xh, pW, proj_b, (float*)d_out, nullptr, nullptr);
}